// round 12
// baseline (speedup 1.0000x reference)
#include <cuda_runtime.h>
#include <cuda_fp16.h>
#include <cstdint>
#include <cstddef>

// Problem constants
#define L_SEQ   2048
#define N_BATCH 2
#define E_DIM   1024
#define H_HEADS 16
#define D_HEAD  64
#define SCALE_F 0.125f
#define ROWS_TOT (L_SEQ * N_BATCH)     // 4096
#define F3       (3 * E_DIM)           // 3072
#define QKV_ROW  (N_BATCH * F3)        // 6144

// ---------------------------------------------------------------------------
// Scratch (no cudaMalloc allowed)
// ---------------------------------------------------------------------------
__device__ __half g_qkvh[(size_t)ROWS_TOT * F3];   // qkv hi (Q pre-scaled)
__device__ __half g_qkvl[(size_t)ROWS_TOT * F3];   // qkv lo (K,V regions used)
__device__ __half g_xh [(size_t)ROWS_TOT * E_DIM];
__device__ __half g_wqh[(size_t)F3 * E_DIM];
__device__ __half g_wql[(size_t)F3 * E_DIM];
__device__ __half g_woh[(size_t)E_DIM * E_DIM];
__device__ __half g_wol[(size_t)E_DIM * E_DIM];
__device__ __half g_ah [(size_t)ROWS_TOT * E_DIM]; // attention out hi

// ---------------------------------------------------------------------------
// Helpers
// ---------------------------------------------------------------------------
__device__ __forceinline__ uint32_t smem_u32(const void* p) {
    uint32_t a;
    asm("{ .reg .u64 t; cvta.to.shared.u64 t, %1; cvt.u32.u64 %0, t; }"
        : "=r"(a) : "l"(p));
    return a;
}

__device__ __forceinline__ void cp_async16(uint32_t dst, const void* src) {
    asm volatile("cp.async.cg.shared.global [%0], [%1], 16;"
                 :: "r"(dst), "l"(src) : "memory");
}
#define CP_COMMIT()  asm volatile("cp.async.commit_group;" ::: "memory")
#define CP_WAIT(n)   asm volatile("cp.async.wait_group %0;" :: "n"(n) : "memory")

// fp16 m16n8k16 MMA, fp32 accumulate
__device__ __forceinline__ void mma16816h(float* d, const uint32_t* a,
                                          const uint32_t* b) {
    asm volatile(
        "mma.sync.aligned.m16n8k16.row.col.f32.f16.f16.f32 "
        "{%0,%1,%2,%3}, {%4,%5,%6,%7}, {%8,%9}, {%0,%1,%2,%3};"
        : "+f"(d[0]), "+f"(d[1]), "+f"(d[2]), "+f"(d[3])
        : "r"(a[0]), "r"(a[1]), "r"(a[2]), "r"(a[3]), "r"(b[0]), "r"(b[1]));
}

__device__ __forceinline__ void ldmx4(uint32_t addr, uint32_t* r) {
    asm volatile("ldmatrix.sync.aligned.m8n8.x4.shared.b16 {%0,%1,%2,%3}, [%4];"
                 : "=r"(r[0]), "=r"(r[1]), "=r"(r[2]), "=r"(r[3]) : "r"(addr));
}
__device__ __forceinline__ void ldmx2(uint32_t addr, uint32_t* r) {
    asm volatile("ldmatrix.sync.aligned.m8n8.x2.shared.b16 {%0,%1}, [%2];"
                 : "=r"(r[0]), "=r"(r[1]) : "r"(addr));
}
__device__ __forceinline__ void ldmx2t(uint32_t addr, uint32_t* r) {
    asm volatile("ldmatrix.sync.aligned.m8n8.x2.trans.shared.b16 {%0,%1}, [%2];"
                 : "=r"(r[0]), "=r"(r[1]) : "r"(addr));
}

// split pair of fp32 into packed fp16 hi and fp16 lo (residual)
__device__ __forceinline__ void split2h(float a, float b, uint32_t& hi, uint32_t& lo) {
    __half2 h = __floats2half2_rn(a, b);
    float ra = a - __low2float(h);
    float rb = b - __high2float(h);
    __half2 l2 = __floats2half2_rn(ra, rb);
    hi = *(uint32_t*)&h;
    lo = *(uint32_t*)&l2;
}
__device__ __forceinline__ uint32_t pack2h(float a, float b) {
    __half2 h = __floats2half2_rn(a, b);
    return *(uint32_t*)&h;
}

// ---------------------------------------------------------------------------
// Fused conversion kernel: x -> hi; w_qkv, w_out -> hi+lo split
// ---------------------------------------------------------------------------
#define NX4   (ROWS_TOT * E_DIM / 4)   // 1048576
#define NWQ4  (F3 * E_DIM / 4)         // 786432
#define NWO4  (E_DIM * E_DIM / 4)      // 262144

__global__ void convert_all(const float* __restrict__ x,
                            const float* __restrict__ wq,
                            const float* __restrict__ wo,
                            __half* __restrict__ xh,
                            __half* __restrict__ wqh, __half* __restrict__ wql,
                            __half* __restrict__ woh, __half* __restrict__ wol)
{
    int i = blockIdx.x * blockDim.x + threadIdx.x;
    if (i < NX4) {
        float4 v = *(const float4*)(x + (size_t)i * 4);
        *(uint2*)(xh + (size_t)i * 4) =
            make_uint2(pack2h(v.x, v.y), pack2h(v.z, v.w));
    } else if (i < NX4 + NWQ4) {
        int j = i - NX4;
        float4 v = *(const float4*)(wq + (size_t)j * 4);
        uint32_t h0, l0, h1, l1;
        split2h(v.x, v.y, h0, l0);
        split2h(v.z, v.w, h1, l1);
        *(uint2*)(wqh + (size_t)j * 4) = make_uint2(h0, h1);
        *(uint2*)(wql + (size_t)j * 4) = make_uint2(l0, l1);
    } else {
        int j = i - NX4 - NWQ4;
        float4 v = *(const float4*)(wo + (size_t)j * 4);
        uint32_t h0, l0, h1, l1;
        split2h(v.x, v.y, h0, l0);
        split2h(v.z, v.w, h1, l1);
        *(uint2*)(woh + (size_t)j * 4) = make_uint2(h0, h1);
        *(uint2*)(wol + (size_t)j * 4) = make_uint2(l0, l1);
    }
}

// ---------------------------------------------------------------------------
// 2-term split-fp16 NT GEMM: C ≈ Ah·Bh^T + Ah·Bl^T.
// 256(M)x128(N)x32 CTA tile, 512 threads (16 warps as 4Mx4N, warp 64x32),
// 3-stage cp.async pipeline. Big M tile halves B traffic through L2.
// ---------------------------------------------------------------------------
#define BK    32
#define PADK  40
#define PADB  (PADK * 2)                   // 80-byte row stride
#define TILE_A_BYTES (256 * PADB)          // 20480
#define TILE_B_BYTES (128 * PADB)          // 10240
#define STAGE_BYTES  (TILE_A_BYTES + 2 * TILE_B_BYTES)   // 40960
#define GEMM_SMEM    (3 * STAGE_BYTES)     // 122880

__global__ __launch_bounds__(512, 1) void gemm_mma(
    const __half* __restrict__ Ah,
    const __half* __restrict__ Bh, const __half* __restrict__ Bl,
    float* __restrict__ C,
    __half* __restrict__ Ch, __half* __restrict__ Cl,
    int split_out, int scale_cols, int M, int Nc, int K)
{
    extern __shared__ __align__(16) char smem[];
    const int tid  = threadIdx.x;
    const int lane = tid & 31;
    const int wid  = tid >> 5;
    const int bm = blockIdx.y * 256;
    const int bn = blockIdx.x * 128;
    const int wm = (wid >> 2) * 64;        // 4 M groups of 64
    const int wn = (wid & 3) * 32;         // 4 N groups of 32

    const __half* Ab  = Ah + (size_t)bm * K;
    const __half* Bhb = Bh + (size_t)bn * K;
    const __half* Blb = Bl + (size_t)bn * K;

    // Loader (512 threads, 2 chunks each per tile set):
    //  A tile: 1024 16B-chunks: ch = tid + it*512; row = ch>>2, col = (ch&3)*8
    //  B tiles: 1024 chunks: ch = tid + it*512; arr = ch>>9, row = (ch>>2)&127
    auto load_stage = [&](int stage, int c) {
        const int k0 = c * BK;
        char* st = smem + stage * STAGE_BYTES;
        #pragma unroll
        for (int it = 0; it < 2; it++) {
            const int ch = tid + it * 512;
            const int r = ch >> 2;
            const int cc = (ch & 3) * 8;
            cp_async16(smem_u32((__half*)st + r * PADK + cc),
                       Ab + (size_t)r * K + k0 + cc);
        }
        #pragma unroll
        for (int it = 0; it < 2; it++) {
            const int ch = tid + it * 512;
            const int arr = ch >> 9;
            const int r = (ch >> 2) & 127;
            const int cc = (ch & 3) * 8;
            __half* dst = (__half*)(st + TILE_A_BYTES + arr * TILE_B_BYTES);
            const __half* src = arr ? Blb : Bhb;
            cp_async16(smem_u32(dst + r * PADK + cc),
                       src + (size_t)r * K + k0 + cc);
        }
        CP_COMMIT();
    };

    float d[4][4][4];
    #pragma unroll
    for (int i = 0; i < 4; i++)
        #pragma unroll
        for (int j = 0; j < 4; j++)
            #pragma unroll
            for (int r = 0; r < 4; r++) d[i][j][r] = 0.0f;

    const int lr4 = lane >> 2;
    const int lk2 = (lane & 3) * 2;

    const uint32_t sbase = smem_u32(smem);
    const uint32_t a_off = (uint32_t)((wm + (lane & 15)) * PADB + ((lane >> 4) * 8) * 2);
    const uint32_t b_off = (uint32_t)((wn + (lane & 7)) * PADB + (((lane >> 3) & 1) * 8) * 2);

    const int nch = K / BK;
    load_stage(0, 0);
    load_stage(1, 1);

    for (int c = 0; c < nch; c++) {
        const int sg = c % 3;
        if (c + 1 < nch) { CP_WAIT(1); } else { CP_WAIT(0); }
        __syncthreads();
        if (c + 2 < nch) load_stage((c + 2) % 3, c + 2);

        const uint32_t sAh = sbase + (uint32_t)(sg * STAGE_BYTES);
        const uint32_t sBh = sAh + TILE_A_BYTES;
        const uint32_t sBl = sBh + TILE_B_BYTES;

        #pragma unroll
        for (int s = 0; s < 2; s++) {
            const uint32_t kof = (uint32_t)(s * 32);
            uint32_t afh[4][4];
            #pragma unroll
            for (int i = 0; i < 4; i++)
                ldmx4(sAh + a_off + (uint32_t)(i * 16 * PADB) + kof, afh[i]);
            #pragma unroll
            for (int j = 0; j < 4; j++) {
                const uint32_t bo = b_off + (uint32_t)(j * 8 * PADB) + kof;
                uint32_t bfh[2], bfl[2];
                ldmx2(sBh + bo, bfh);
                ldmx2(sBl + bo, bfl);
                #pragma unroll
                for (int i = 0; i < 4; i++) mma16816h(d[i][j], afh[i], bfh);
                #pragma unroll
                for (int i = 0; i < 4; i++) mma16816h(d[i][j], afh[i], bfl);
            }
        }
    }

    if (split_out) {
        #pragma unroll
        for (int i = 0; i < 4; i++) {
            const int row = bm + wm + i * 16 + lr4;
            #pragma unroll
            for (int j = 0; j < 4; j++) {
                const int col = bn + wn + j * 8 + lk2;
                const float sc = (col < scale_cols) ? SCALE_F : 1.0f;
                uint32_t hh, ll;
                split2h(d[i][j][0] * sc, d[i][j][1] * sc, hh, ll);
                *(uint32_t*)(Ch + (size_t)row * Nc + col) = hh;
                *(uint32_t*)(Cl + (size_t)row * Nc + col) = ll;
                split2h(d[i][j][2] * sc, d[i][j][3] * sc, hh, ll);
                *(uint32_t*)(Ch + (size_t)(row + 8) * Nc + col) = hh;
                *(uint32_t*)(Cl + (size_t)(row + 8) * Nc + col) = ll;
            }
        }
    } else {
        #pragma unroll
        for (int i = 0; i < 4; i++) {
            const int row = bm + wm + i * 16 + lr4;
            #pragma unroll
            for (int j = 0; j < 4; j++) {
                const int col = bn + wn + j * 8 + lk2;
                *(float2*)(C + (size_t)row * Nc + col) =
                    make_float2(d[i][j][0], d[i][j][1]);
                *(float2*)(C + (size_t)(row + 8) * Nc + col) =
                    make_float2(d[i][j][2], d[i][j][3]);
            }
        }
    }
}

// ---------------------------------------------------------------------------
// Flash attention, fp16 2-term split, causal, 2-stage cp.async K/V prefetch.
// ---------------------------------------------------------------------------
#define FPAD 72
#define FTILE (64 * FPAD)                  // halfs per K/V tile
#define FBUF_BYTES (4 * FTILE * 2)         // Kh,Kl,Vh,Vl = 36864
#define FLASH_SMEM (2 * FBUF_BYTES)        // 73728

__global__ __launch_bounds__(256) void flash_mma(
    const __half* __restrict__ qkvh,
    const __half* __restrict__ qkvl,
    __half* __restrict__ ah)
{
    extern __shared__ __align__(16) char fsm[];

    const int tid  = threadIdx.x;
    const int lane = tid & 31;
    const int w    = tid >> 5;
    const int qi   = (int)gridDim.x - 1 - (int)blockIdx.x;
    const int by   = blockIdx.y;
    const int n    = by >> 4;
    const int h    = by & 15;
    const int q0   = qi * 128;
    const int lr4  = lane >> 2;
    const int lk2  = (lane & 3) * 2;

    const __half* qhp = qkvh + (size_t)n * F3 + h * D_HEAD;
    const __half* khp = qhp + E_DIM;
    const __half* klp = qkvl + (size_t)n * F3 + h * D_HEAD + E_DIM;
    const __half* vhp = qhp + 2 * E_DIM;
    const __half* vlp = klp + E_DIM;

    // ---- Phase 1: stage Q hi, build fragments ----
    {
        __half* Qsh = (__half*)fsm;
        #pragma unroll
        for (int i = 0; i < 4; i++) {
            int ch = tid + i * 256;
            int r  = ch >> 3;
            int c  = (ch & 7) * 8;
            *(uint4*)&Qsh[r * FPAD + c] =
                *(const uint4*)(qhp + (size_t)(q0 + r) * QKV_ROW + c);
        }
    }
    __syncthreads();

    uint32_t qh[4][4];
    {
        const uint32_t qa = (uint32_t)(((w * 16 + (lane & 15)) * FPAD +
                                        (lane >> 4) * 8) * 2);
        const uint32_t sQh = smem_u32(fsm);
        #pragma unroll
        for (int st = 0; st < 4; st++)
            ldmx4(sQh + qa + st * 32, qh[st]);
    }
    __syncthreads();

    const __half* fsrc[4] = {khp, klp, vhp, vlp};
    auto load_tile = [&](int buf, int kt) {
        char* base = fsm + buf * FBUF_BYTES;
        #pragma unroll
        for (int i = 0; i < 8; i++) {
            int ch = tid + i * 256;
            int t  = ch >> 9;
            int rr = (ch >> 3) & 63;
            int cc = (ch & 7) * 8;
            __half* dst = (__half*)base + t * FTILE + rr * FPAD + cc;
            cp_async16(smem_u32(dst),
                       fsrc[t] + (size_t)(kt * 64 + rr) * QKV_ROW + cc);
        }
        CP_COMMIT();
    };

    float rm0 = -1e30f, rm1 = -1e30f, rl0 = 0.0f, rl1 = 0.0f;
    float o[8][4];
    #pragma unroll
    for (int j = 0; j < 8; j++)
        #pragma unroll
        for (int r = 0; r < 4; r++) o[j][r] = 0.0f;

    const int nkt = 2 * qi + 2;
    load_tile(0, 0);

    for (int kt = 0; kt < nkt; kt++) {
        const int b = kt & 1;
        CP_WAIT(0);
        __syncthreads();
        if (kt + 1 < nkt) load_tile(b ^ 1, kt + 1);

        const __half* Kh = (const __half*)(fsm + b * FBUF_BYTES);
        const __half* Kl = Kh + FTILE;
        const __half* Vh = Kl + FTILE;
        const __half* Vl = Vh + FTILE;

        float s[8][4];
        #pragma unroll
        for (int j = 0; j < 8; j++)
            #pragma unroll
            for (int r = 0; r < 4; r++) s[j][r] = 0.0f;

        #pragma unroll
        for (int st = 0; st < 4; st++) {
            const int kb = st * 16 + lk2;
            #pragma unroll
            for (int jp = 0; jp < 4; jp++) {
                const int n0 = (2 * jp)     * 8 + lr4;
                const int n1 = (2 * jp + 1) * 8 + lr4;
                uint32_t bh0[2], bl0[2], bh1[2], bl1[2];
                bh0[0] = *(const uint32_t*)(Kh + n0 * FPAD + kb);
                bh0[1] = *(const uint32_t*)(Kh + n0 * FPAD + kb + 8);
                bh1[0] = *(const uint32_t*)(Kh + n1 * FPAD + kb);
                bh1[1] = *(const uint32_t*)(Kh + n1 * FPAD + kb + 8);
                bl0[0] = *(const uint32_t*)(Kl + n0 * FPAD + kb);
                bl0[1] = *(const uint32_t*)(Kl + n0 * FPAD + kb + 8);
                bl1[0] = *(const uint32_t*)(Kl + n1 * FPAD + kb);
                bl1[1] = *(const uint32_t*)(Kl + n1 * FPAD + kb + 8);
                mma16816h(s[2*jp],   qh[st], bh0);
                mma16816h(s[2*jp+1], qh[st], bh1);
                mma16816h(s[2*jp],   qh[st], bl0);
                mma16816h(s[2*jp+1], qh[st], bl1);
            }
        }

        if (kt >= 2 * qi) {
            const int r0g = q0 + w * 16 + lr4;
            const int r1g = r0g + 8;
            #pragma unroll
            for (int j = 0; j < 8; j++) {
                const int cg = kt * 64 + j * 8 + lk2;
                if (cg     > r0g) s[j][0] = -1e30f;
                if (cg + 1 > r0g) s[j][1] = -1e30f;
                if (cg     > r1g) s[j][2] = -1e30f;
                if (cg + 1 > r1g) s[j][3] = -1e30f;
            }
        }

        float mx0 = -1e30f, mx1 = -1e30f;
        #pragma unroll
        for (int j = 0; j < 8; j++) {
            mx0 = fmaxf(mx0, fmaxf(s[j][0], s[j][1]));
            mx1 = fmaxf(mx1, fmaxf(s[j][2], s[j][3]));
        }
        mx0 = fmaxf(mx0, __shfl_xor_sync(0xffffffffu, mx0, 1));
        mx0 = fmaxf(mx0, __shfl_xor_sync(0xffffffffu, mx0, 2));
        mx1 = fmaxf(mx1, __shfl_xor_sync(0xffffffffu, mx1, 1));
        mx1 = fmaxf(mx1, __shfl_xor_sync(0xffffffffu, mx1, 2));

        const float mn0 = fmaxf(rm0, mx0);
        const float mn1 = fmaxf(rm1, mx1);
        const float a0 = __expf(rm0 - mn0);
        const float a1 = __expf(rm1 - mn1);
        rm0 = mn0; rm1 = mn1;

        float sum0 = 0.0f, sum1 = 0.0f;
        #pragma unroll
        for (int j = 0; j < 8; j++) {
            s[j][0] = __expf(s[j][0] - mn0);
            s[j][1] = __expf(s[j][1] - mn0);
            s[j][2] = __expf(s[j][2] - mn1);
            s[j][3] = __expf(s[j][3] - mn1);
            sum0 += s[j][0] + s[j][1];
            sum1 += s[j][2] + s[j][3];
        }
        sum0 += __shfl_xor_sync(0xffffffffu, sum0, 1);
        sum0 += __shfl_xor_sync(0xffffffffu, sum0, 2);
        sum1 += __shfl_xor_sync(0xffffffffu, sum1, 1);
        sum1 += __shfl_xor_sync(0xffffffffu, sum1, 2);
        rl0 = rl0 * a0 + sum0;
        rl1 = rl1 * a1 + sum1;

        #pragma unroll
        for (int j = 0; j < 8; j++) {
            o[j][0] *= a0; o[j][1] *= a0;
            o[j][2] *= a1; o[j][3] *= a1;
        }

        #pragma unroll
        for (int st = 0; st < 4; st++) {
            uint32_t pah[4];
            pah[0] = pack2h(s[2*st][0],   s[2*st][1]);
            pah[1] = pack2h(s[2*st][2],   s[2*st][3]);
            pah[2] = pack2h(s[2*st+1][0], s[2*st+1][1]);
            pah[3] = pack2h(s[2*st+1][2], s[2*st+1][3]);
            const int vrow = st * 16 + (lane & 15);
            #pragma unroll
            for (int jp = 0; jp < 4; jp++) {
                const int j0 = 2 * jp, j1 = 2 * jp + 1;
                uint32_t bh0[2], bl0[2], bh1[2], bl1[2];
                ldmx2t(smem_u32(Vh + vrow * FPAD + j0 * 8), bh0);
                ldmx2t(smem_u32(Vl + vrow * FPAD + j0 * 8), bl0);
                ldmx2t(smem_u32(Vh + vrow * FPAD + j1 * 8), bh1);
                ldmx2t(smem_u32(Vl + vrow * FPAD + j1 * 8), bl1);
                mma16816h(o[j0], pah, bh0);
                mma16816h(o[j1], pah, bh1);
                mma16816h(o[j0], pah, bl0);
                mma16816h(o[j1], pah, bl1);
            }
        }
    }

    const float inv0 = 1.0f / rl0;
    const float inv1 = 1.0f / rl1;
    const int r0g = q0 + w * 16 + lr4;
    const size_t row0 = (size_t)(r0g * N_BATCH + n) * E_DIM;
    const size_t row1 = (size_t)((r0g + 8) * N_BATCH + n) * E_DIM;
    #pragma unroll
    for (int j = 0; j < 8; j++) {
        const int col = h * D_HEAD + j * 8 + lk2;
        *(uint32_t*)(ah + row0 + col) = pack2h(o[j][0] * inv0, o[j][1] * inv0);
        *(uint32_t*)(ah + row1 + col) = pack2h(o[j][2] * inv1, o[j][3] * inv1);
    }
}

// ---------------------------------------------------------------------------
extern "C" void kernel_launch(void* const* d_in, const int* in_sizes, int n_in,
                              void* d_out, int out_size)
{
    const float* x     = (const float*)d_in[0];
    const float* w_qkv = (const float*)d_in[1];
    const float* w_out = (const float*)d_in[2];
    float* out = (float*)d_out;

    __half *qkvh, *qkvl, *xh, *wqh, *wql, *woh, *wol, *ah;
    cudaGetSymbolAddress((void**)&qkvh, g_qkvh);
    cudaGetSymbolAddress((void**)&qkvl, g_qkvl);
    cudaGetSymbolAddress((void**)&xh,   g_xh);
    cudaGetSymbolAddress((void**)&wqh,  g_wqh);
    cudaGetSymbolAddress((void**)&wql,  g_wql);
    cudaGetSymbolAddress((void**)&woh,  g_woh);
    cudaGetSymbolAddress((void**)&wol,  g_wol);
    cudaGetSymbolAddress((void**)&ah,   g_ah);

    cudaFuncSetAttribute(gemm_mma,
                         cudaFuncAttributeMaxDynamicSharedMemorySize, GEMM_SMEM);
    cudaFuncSetAttribute(flash_mma,
                         cudaFuncAttributeMaxDynamicSharedMemorySize, FLASH_SMEM);

    // 0) fused conversions
    {
        int total = NX4 + NWQ4 + NWO4;
        convert_all<<<(total + 255) / 256, 256>>>(
            x, w_qkv, w_out, xh, wqh, wql, woh, wol);
    }

    // 1) QKV projection -> pre-split fp16 (Q region scaled by 1/8)
    gemm_mma<<<dim3(F3 / 128, ROWS_TOT / 256), 512, GEMM_SMEM>>>(
        xh, wqh, wql, nullptr, qkvh, qkvl, 1, E_DIM, ROWS_TOT, F3, E_DIM);

    // 2) Causal flash attention -> fp16 hi
    flash_mma<<<dim3(L_SEQ / 128, N_BATCH * H_HEADS), 256, FLASH_SMEM>>>(
        qkvh, qkvl, ah);

    // 3) Output projection -> fp32 out
    gemm_mma<<<dim3(E_DIM / 128, ROWS_TOT / 256), 512, GEMM_SMEM>>>(
        ah, woh, wol, out, nullptr, nullptr, 0, 0, ROWS_TOT, E_DIM, E_DIM);
}

// round 13
// speedup vs baseline: 1.5051x; 1.5051x over previous
#include <cuda_runtime.h>
#include <cuda_fp16.h>
#include <cstdint>
#include <cstddef>

// Problem constants
#define L_SEQ   2048
#define N_BATCH 2
#define E_DIM   1024
#define H_HEADS 16
#define D_HEAD  64
#define SCALE_F 0.125f
#define ROWS_TOT (L_SEQ * N_BATCH)     // 4096
#define F3       (3 * E_DIM)           // 3072
#define QKV_ROW  (N_BATCH * F3)        // 6144

// ---------------------------------------------------------------------------
// Scratch (no cudaMalloc allowed)
// ---------------------------------------------------------------------------
__device__ __half g_qkvh[(size_t)ROWS_TOT * F3];   // qkv fp16 (Q pre-scaled)
__device__ __half g_xh [(size_t)ROWS_TOT * E_DIM];
__device__ __half g_wqh[(size_t)F3 * E_DIM];
__device__ __half g_woh[(size_t)E_DIM * E_DIM];
__device__ __half g_ah [(size_t)ROWS_TOT * E_DIM]; // attention out fp16

// ---------------------------------------------------------------------------
// Helpers
// ---------------------------------------------------------------------------
__device__ __forceinline__ uint32_t smem_u32(const void* p) {
    uint32_t a;
    asm("{ .reg .u64 t; cvta.to.shared.u64 t, %1; cvt.u32.u64 %0, t; }"
        : "=r"(a) : "l"(p));
    return a;
}

__device__ __forceinline__ void cp_async16(uint32_t dst, const void* src) {
    asm volatile("cp.async.cg.shared.global [%0], [%1], 16;"
                 :: "r"(dst), "l"(src) : "memory");
}
#define CP_COMMIT()  asm volatile("cp.async.commit_group;" ::: "memory")
#define CP_WAIT(n)   asm volatile("cp.async.wait_group %0;" :: "n"(n) : "memory")

// fp16 m16n8k16 MMA, fp32 accumulate
__device__ __forceinline__ void mma16816h(float* d, const uint32_t* a,
                                          const uint32_t* b) {
    asm volatile(
        "mma.sync.aligned.m16n8k16.row.col.f32.f16.f16.f32 "
        "{%0,%1,%2,%3}, {%4,%5,%6,%7}, {%8,%9}, {%0,%1,%2,%3};"
        : "+f"(d[0]), "+f"(d[1]), "+f"(d[2]), "+f"(d[3])
        : "r"(a[0]), "r"(a[1]), "r"(a[2]), "r"(a[3]), "r"(b[0]), "r"(b[1]));
}

__device__ __forceinline__ void ldmx4(uint32_t addr, uint32_t* r) {
    asm volatile("ldmatrix.sync.aligned.m8n8.x4.shared.b16 {%0,%1,%2,%3}, [%4];"
                 : "=r"(r[0]), "=r"(r[1]), "=r"(r[2]), "=r"(r[3]) : "r"(addr));
}
__device__ __forceinline__ void ldmx2(uint32_t addr, uint32_t* r) {
    asm volatile("ldmatrix.sync.aligned.m8n8.x2.shared.b16 {%0,%1}, [%2];"
                 : "=r"(r[0]), "=r"(r[1]) : "r"(addr));
}
__device__ __forceinline__ void ldmx2t(uint32_t addr, uint32_t* r) {
    asm volatile("ldmatrix.sync.aligned.m8n8.x2.trans.shared.b16 {%0,%1}, [%2];"
                 : "=r"(r[0]), "=r"(r[1]) : "r"(addr));
}

__device__ __forceinline__ uint32_t pack2h(float a, float b) {
    __half2 h = __floats2half2_rn(a, b);
    return *(uint32_t*)&h;
}

// ---------------------------------------------------------------------------
// Fused conversion kernel: x, w_qkv, w_out -> fp16
// ---------------------------------------------------------------------------
#define NX4   (ROWS_TOT * E_DIM / 4)   // 1048576
#define NWQ4  (F3 * E_DIM / 4)         // 786432
#define NWO4  (E_DIM * E_DIM / 4)      // 262144

__global__ void convert_all(const float* __restrict__ x,
                            const float* __restrict__ wq,
                            const float* __restrict__ wo,
                            __half* __restrict__ xh,
                            __half* __restrict__ wqh,
                            __half* __restrict__ woh)
{
    int i = blockIdx.x * blockDim.x + threadIdx.x;
    const float* src;
    __half* dst;
    int j;
    if (i < NX4)                 { src = x;  dst = xh;  j = i; }
    else if (i < NX4 + NWQ4)     { src = wq; dst = wqh; j = i - NX4; }
    else                         { src = wo; dst = woh; j = i - NX4 - NWQ4; }
    float4 v = *(const float4*)(src + (size_t)j * 4);
    *(uint2*)(dst + (size_t)j * 4) =
        make_uint2(pack2h(v.x, v.y), pack2h(v.z, v.w));
}

// ---------------------------------------------------------------------------
// fp16 NT GEMM: C = A B^T (single term).
// 256(M)x128(N)x32 CTA tile, 512 threads (16 warps as 4Mx4N, warp 64x32),
// 3-stage cp.async pipeline.
// ---------------------------------------------------------------------------
#define BK    32
#define PADK  40
#define PADB  (PADK * 2)                   // 80-byte row stride
#define TILE_A_BYTES (256 * PADB)          // 20480
#define TILE_B_BYTES (128 * PADB)          // 10240
#define STAGE_BYTES  (TILE_A_BYTES + TILE_B_BYTES)       // 30720
#define GEMM_SMEM    (3 * STAGE_BYTES)     // 92160

__global__ __launch_bounds__(512, 1) void gemm_mma(
    const __half* __restrict__ Ah,
    const __half* __restrict__ Bh,
    float* __restrict__ C,
    __half* __restrict__ Ch,
    int split_out, int scale_cols, int M, int Nc, int K)
{
    extern __shared__ __align__(16) char smem[];
    const int tid  = threadIdx.x;
    const int lane = tid & 31;
    const int wid  = tid >> 5;
    const int bm = blockIdx.y * 256;
    const int bn = blockIdx.x * 128;
    const int wm = (wid >> 2) * 64;
    const int wn = (wid & 3) * 32;

    const __half* Ab = Ah + (size_t)bm * K;
    const __half* Bb = Bh + (size_t)bn * K;

    // Loader: A = 1024 16B-chunks (2/thread), B = 512 chunks (1/thread)
    auto load_stage = [&](int stage, int c) {
        const int k0 = c * BK;
        char* st = smem + stage * STAGE_BYTES;
        #pragma unroll
        for (int it = 0; it < 2; it++) {
            const int ch = tid + it * 512;
            const int r = ch >> 2;
            const int cc = (ch & 3) * 8;
            cp_async16(smem_u32((__half*)st + r * PADK + cc),
                       Ab + (size_t)r * K + k0 + cc);
        }
        {
            const int r = tid >> 2;
            const int cc = (tid & 3) * 8;
            __half* dst = (__half*)(st + TILE_A_BYTES);
            cp_async16(smem_u32(dst + r * PADK + cc),
                       Bb + (size_t)r * K + k0 + cc);
        }
        CP_COMMIT();
    };

    float d[4][4][4];
    #pragma unroll
    for (int i = 0; i < 4; i++)
        #pragma unroll
        for (int j = 0; j < 4; j++)
            #pragma unroll
            for (int r = 0; r < 4; r++) d[i][j][r] = 0.0f;

    const int lr4 = lane >> 2;
    const int lk2 = (lane & 3) * 2;

    const uint32_t sbase = smem_u32(smem);
    const uint32_t a_off = (uint32_t)((wm + (lane & 15)) * PADB + ((lane >> 4) * 8) * 2);
    const uint32_t b_off = (uint32_t)((wn + (lane & 7)) * PADB + (((lane >> 3) & 1) * 8) * 2);

    const int nch = K / BK;
    load_stage(0, 0);
    load_stage(1, 1);

    for (int c = 0; c < nch; c++) {
        const int sg = c % 3;
        if (c + 1 < nch) { CP_WAIT(1); } else { CP_WAIT(0); }
        __syncthreads();
        if (c + 2 < nch) load_stage((c + 2) % 3, c + 2);

        const uint32_t sA = sbase + (uint32_t)(sg * STAGE_BYTES);
        const uint32_t sB = sA + TILE_A_BYTES;

        #pragma unroll
        for (int s = 0; s < 2; s++) {
            const uint32_t kof = (uint32_t)(s * 32);
            uint32_t af[4][4];
            #pragma unroll
            for (int i = 0; i < 4; i++)
                ldmx4(sA + a_off + (uint32_t)(i * 16 * PADB) + kof, af[i]);
            #pragma unroll
            for (int j = 0; j < 4; j++) {
                uint32_t bf[2];
                ldmx2(sB + b_off + (uint32_t)(j * 8 * PADB) + kof, bf);
                #pragma unroll
                for (int i = 0; i < 4; i++) mma16816h(d[i][j], af[i], bf);
            }
        }
    }

    if (split_out) {
        #pragma unroll
        for (int i = 0; i < 4; i++) {
            const int row = bm + wm + i * 16 + lr4;
            #pragma unroll
            for (int j = 0; j < 4; j++) {
                const int col = bn + wn + j * 8 + lk2;
                const float sc = (col < scale_cols) ? SCALE_F : 1.0f;
                *(uint32_t*)(Ch + (size_t)row * Nc + col) =
                    pack2h(d[i][j][0] * sc, d[i][j][1] * sc);
                *(uint32_t*)(Ch + (size_t)(row + 8) * Nc + col) =
                    pack2h(d[i][j][2] * sc, d[i][j][3] * sc);
            }
        }
    } else {
        #pragma unroll
        for (int i = 0; i < 4; i++) {
            const int row = bm + wm + i * 16 + lr4;
            #pragma unroll
            for (int j = 0; j < 4; j++) {
                const int col = bn + wn + j * 8 + lk2;
                *(float2*)(C + (size_t)row * Nc + col) =
                    make_float2(d[i][j][0], d[i][j][1]);
                *(float2*)(C + (size_t)(row + 8) * Nc + col) =
                    make_float2(d[i][j][2], d[i][j][3]);
            }
        }
    }
}

// ---------------------------------------------------------------------------
// Flash attention, pure fp16, causal, 2-stage cp.async K/V prefetch.
// ---------------------------------------------------------------------------
#define FPAD 72
#define FTILE (64 * FPAD)                  // halfs per K or V tile
#define FBUF_BYTES (2 * FTILE * 2)         // Kh,Vh = 18432
#define FLASH_SMEM (2 * FBUF_BYTES)        // 36864

__global__ __launch_bounds__(256) void flash_mma(
    const __half* __restrict__ qkvh,
    __half* __restrict__ ah)
{
    extern __shared__ __align__(16) char fsm[];

    const int tid  = threadIdx.x;
    const int lane = tid & 31;
    const int w    = tid >> 5;
    const int qi   = (int)gridDim.x - 1 - (int)blockIdx.x;
    const int by   = blockIdx.y;
    const int n    = by >> 4;
    const int h    = by & 15;
    const int q0   = qi * 128;
    const int lr4  = lane >> 2;
    const int lk2  = (lane & 3) * 2;

    const __half* qhp = qkvh + (size_t)n * F3 + h * D_HEAD;
    const __half* khp = qhp + E_DIM;
    const __half* vhp = qhp + 2 * E_DIM;

    // ---- Phase 1: stage Q in buffer 0 (128*FPAD*2 = 18432 B fits), frags ----
    {
        __half* Qsh = (__half*)fsm;
        #pragma unroll
        for (int i = 0; i < 4; i++) {
            int ch = tid + i * 256;
            int r  = ch >> 3;
            int c  = (ch & 7) * 8;
            *(uint4*)&Qsh[r * FPAD + c] =
                *(const uint4*)(qhp + (size_t)(q0 + r) * QKV_ROW + c);
        }
    }
    __syncthreads();

    uint32_t qh[4][4];
    {
        const uint32_t qa = (uint32_t)(((w * 16 + (lane & 15)) * FPAD +
                                        (lane >> 4) * 8) * 2);
        const uint32_t sQh = smem_u32(fsm);
        #pragma unroll
        for (int st = 0; st < 4; st++)
            ldmx4(sQh + qa + st * 32, qh[st]);
    }
    __syncthreads();

    const __half* fsrc[2] = {khp, vhp};
    // 1024 chunks per tile pair (2 arrays x 64 rows x 8 chunks) = 4/thread
    auto load_tile = [&](int buf, int kt) {
        char* base = fsm + buf * FBUF_BYTES;
        #pragma unroll
        for (int i = 0; i < 4; i++) {
            int ch = tid + i * 256;
            int t  = ch >> 9;
            int rr = (ch >> 3) & 63;
            int cc = (ch & 7) * 8;
            __half* dst = (__half*)base + t * FTILE + rr * FPAD + cc;
            cp_async16(smem_u32(dst),
                       fsrc[t] + (size_t)(kt * 64 + rr) * QKV_ROW + cc);
        }
        CP_COMMIT();
    };

    float rm0 = -1e30f, rm1 = -1e30f, rl0 = 0.0f, rl1 = 0.0f;
    float o[8][4];
    #pragma unroll
    for (int j = 0; j < 8; j++)
        #pragma unroll
        for (int r = 0; r < 4; r++) o[j][r] = 0.0f;

    const int nkt = 2 * qi + 2;
    load_tile(0, 0);

    for (int kt = 0; kt < nkt; kt++) {
        const int b = kt & 1;
        CP_WAIT(0);
        __syncthreads();
        if (kt + 1 < nkt) load_tile(b ^ 1, kt + 1);

        const __half* Kh = (const __half*)(fsm + b * FBUF_BYTES);
        const __half* Vh = Kh + FTILE;

        // ---- S = Q K^T ----
        float s[8][4];
        #pragma unroll
        for (int j = 0; j < 8; j++)
            #pragma unroll
            for (int r = 0; r < 4; r++) s[j][r] = 0.0f;

        #pragma unroll
        for (int st = 0; st < 4; st++) {
            const int kb = st * 16 + lk2;
            #pragma unroll
            for (int jp = 0; jp < 4; jp++) {
                const int n0 = (2 * jp)     * 8 + lr4;
                const int n1 = (2 * jp + 1) * 8 + lr4;
                uint32_t bh0[2], bh1[2];
                bh0[0] = *(const uint32_t*)(Kh + n0 * FPAD + kb);
                bh0[1] = *(const uint32_t*)(Kh + n0 * FPAD + kb + 8);
                bh1[0] = *(const uint32_t*)(Kh + n1 * FPAD + kb);
                bh1[1] = *(const uint32_t*)(Kh + n1 * FPAD + kb + 8);
                mma16816h(s[2*jp],   qh[st], bh0);
                mma16816h(s[2*jp+1], qh[st], bh1);
            }
        }

        // ---- causal mask ----
        if (kt >= 2 * qi) {
            const int r0g = q0 + w * 16 + lr4;
            const int r1g = r0g + 8;
            #pragma unroll
            for (int j = 0; j < 8; j++) {
                const int cg = kt * 64 + j * 8 + lk2;
                if (cg     > r0g) s[j][0] = -1e30f;
                if (cg + 1 > r0g) s[j][1] = -1e30f;
                if (cg     > r1g) s[j][2] = -1e30f;
                if (cg + 1 > r1g) s[j][3] = -1e30f;
            }
        }

        // ---- online softmax ----
        float mx0 = -1e30f, mx1 = -1e30f;
        #pragma unroll
        for (int j = 0; j < 8; j++) {
            mx0 = fmaxf(mx0, fmaxf(s[j][0], s[j][1]));
            mx1 = fmaxf(mx1, fmaxf(s[j][2], s[j][3]));
        }
        mx0 = fmaxf(mx0, __shfl_xor_sync(0xffffffffu, mx0, 1));
        mx0 = fmaxf(mx0, __shfl_xor_sync(0xffffffffu, mx0, 2));
        mx1 = fmaxf(mx1, __shfl_xor_sync(0xffffffffu, mx1, 1));
        mx1 = fmaxf(mx1, __shfl_xor_sync(0xffffffffu, mx1, 2));

        const float mn0 = fmaxf(rm0, mx0);
        const float mn1 = fmaxf(rm1, mx1);
        const float a0 = __expf(rm0 - mn0);
        const float a1 = __expf(rm1 - mn1);
        rm0 = mn0; rm1 = mn1;

        float sum0 = 0.0f, sum1 = 0.0f;
        #pragma unroll
        for (int j = 0; j < 8; j++) {
            s[j][0] = __expf(s[j][0] - mn0);
            s[j][1] = __expf(s[j][1] - mn0);
            s[j][2] = __expf(s[j][2] - mn1);
            s[j][3] = __expf(s[j][3] - mn1);
            sum0 += s[j][0] + s[j][1];
            sum1 += s[j][2] + s[j][3];
        }
        sum0 += __shfl_xor_sync(0xffffffffu, sum0, 1);
        sum0 += __shfl_xor_sync(0xffffffffu, sum0, 2);
        sum1 += __shfl_xor_sync(0xffffffffu, sum1, 1);
        sum1 += __shfl_xor_sync(0xffffffffu, sum1, 2);
        rl0 = rl0 * a0 + sum0;
        rl1 = rl1 * a1 + sum1;

        #pragma unroll
        for (int j = 0; j < 8; j++) {
            o[j][0] *= a0; o[j][1] *= a0;
            o[j][2] *= a1; o[j][3] *= a1;
        }

        // ---- O += P V ----
        #pragma unroll
        for (int st = 0; st < 4; st++) {
            uint32_t pah[4];
            pah[0] = pack2h(s[2*st][0],   s[2*st][1]);
            pah[1] = pack2h(s[2*st][2],   s[2*st][3]);
            pah[2] = pack2h(s[2*st+1][0], s[2*st+1][1]);
            pah[3] = pack2h(s[2*st+1][2], s[2*st+1][3]);
            const int vrow = st * 16 + (lane & 15);
            #pragma unroll
            for (int jp = 0; jp < 4; jp++) {
                const int j0 = 2 * jp, j1 = 2 * jp + 1;
                uint32_t bh0[2], bh1[2];
                ldmx2t(smem_u32(Vh + vrow * FPAD + j0 * 8), bh0);
                ldmx2t(smem_u32(Vh + vrow * FPAD + j1 * 8), bh1);
                mma16816h(o[j0], pah, bh0);
                mma16816h(o[j1], pah, bh1);
            }
        }
    }

    // ---- epilogue: normalize, write fp16 ----
    const float inv0 = 1.0f / rl0;
    const float inv1 = 1.0f / rl1;
    const int r0g = q0 + w * 16 + lr4;
    const size_t row0 = (size_t)(r0g * N_BATCH + n) * E_DIM;
    const size_t row1 = (size_t)((r0g + 8) * N_BATCH + n) * E_DIM;
    #pragma unroll
    for (int j = 0; j < 8; j++) {
        const int col = h * D_HEAD + j * 8 + lk2;
        *(uint32_t*)(ah + row0 + col) = pack2h(o[j][0] * inv0, o[j][1] * inv0);
        *(uint32_t*)(ah + row1 + col) = pack2h(o[j][2] * inv1, o[j][3] * inv1);
    }
}

// ---------------------------------------------------------------------------
extern "C" void kernel_launch(void* const* d_in, const int* in_sizes, int n_in,
                              void* d_out, int out_size)
{
    const float* x     = (const float*)d_in[0];
    const float* w_qkv = (const float*)d_in[1];
    const float* w_out = (const float*)d_in[2];
    float* out = (float*)d_out;

    __half *qkvh, *xh, *wqh, *woh, *ah;
    cudaGetSymbolAddress((void**)&qkvh, g_qkvh);
    cudaGetSymbolAddress((void**)&xh,   g_xh);
    cudaGetSymbolAddress((void**)&wqh,  g_wqh);
    cudaGetSymbolAddress((void**)&woh,  g_woh);
    cudaGetSymbolAddress((void**)&ah,   g_ah);

    cudaFuncSetAttribute(gemm_mma,
                         cudaFuncAttributeMaxDynamicSharedMemorySize, GEMM_SMEM);
    cudaFuncSetAttribute(flash_mma,
                         cudaFuncAttributeMaxDynamicSharedMemorySize, FLASH_SMEM);

    // 0) fused conversions
    {
        int total = NX4 + NWQ4 + NWO4;
        convert_all<<<(total + 255) / 256, 256>>>(x, w_qkv, w_out, xh, wqh, woh);
    }

    // 1) QKV projection -> fp16 (Q region scaled by 1/8)
    gemm_mma<<<dim3(F3 / 128, ROWS_TOT / 256), 512, GEMM_SMEM>>>(
        xh, wqh, nullptr, qkvh, 1, E_DIM, ROWS_TOT, F3, E_DIM);

    // 2) Causal flash attention -> fp16
    flash_mma<<<dim3(L_SEQ / 128, N_BATCH * H_HEADS), 256, FLASH_SMEM>>>(
        qkvh, ah);

    // 3) Output projection -> fp32 out
    gemm_mma<<<dim3(E_DIM / 128, ROWS_TOT / 256), 512, GEMM_SMEM>>>(
        ah, woh, out, nullptr, 0, 0, ROWS_TOT, E_DIM, E_DIM);
}

// round 14
// speedup vs baseline: 1.6250x; 1.0796x over previous
#include <cuda_runtime.h>
#include <cuda_fp16.h>
#include <cstdint>
#include <cstddef>

// Problem constants
#define L_SEQ   2048
#define N_BATCH 2
#define E_DIM   1024
#define H_HEADS 16
#define D_HEAD  64
#define SCALE_F 0.125f
#define ROWS_TOT (L_SEQ * N_BATCH)     // 4096
#define F3       (3 * E_DIM)           // 3072
#define QKV_ROW  (N_BATCH * F3)        // 6144

// ---------------------------------------------------------------------------
// Scratch (no cudaMalloc allowed)
// ---------------------------------------------------------------------------
__device__ __half g_qkvh[(size_t)ROWS_TOT * F3];   // qkv fp16 (Q pre-scaled)
__device__ __half g_xh [(size_t)ROWS_TOT * E_DIM];
__device__ __half g_wqh[(size_t)F3 * E_DIM];
__device__ __half g_woh[(size_t)E_DIM * E_DIM];
__device__ __half g_ah [(size_t)ROWS_TOT * E_DIM]; // attention out fp16

// ---------------------------------------------------------------------------
// Helpers
// ---------------------------------------------------------------------------
__device__ __forceinline__ uint32_t smem_u32(const void* p) {
    uint32_t a;
    asm("{ .reg .u64 t; cvta.to.shared.u64 t, %1; cvt.u32.u64 %0, t; }"
        : "=r"(a) : "l"(p));
    return a;
}

__device__ __forceinline__ void cp_async16(uint32_t dst, const void* src) {
    asm volatile("cp.async.cg.shared.global [%0], [%1], 16;"
                 :: "r"(dst), "l"(src) : "memory");
}
#define CP_COMMIT()  asm volatile("cp.async.commit_group;" ::: "memory")
#define CP_WAIT(n)   asm volatile("cp.async.wait_group %0;" :: "n"(n) : "memory")

// fp16 m16n8k16 MMA, fp32 accumulate
__device__ __forceinline__ void mma16816h(float* d, const uint32_t* a,
                                          const uint32_t* b) {
    asm volatile(
        "mma.sync.aligned.m16n8k16.row.col.f32.f16.f16.f32 "
        "{%0,%1,%2,%3}, {%4,%5,%6,%7}, {%8,%9}, {%0,%1,%2,%3};"
        : "+f"(d[0]), "+f"(d[1]), "+f"(d[2]), "+f"(d[3])
        : "r"(a[0]), "r"(a[1]), "r"(a[2]), "r"(a[3]), "r"(b[0]), "r"(b[1]));
}

__device__ __forceinline__ void ldmx4(uint32_t addr, uint32_t* r) {
    asm volatile("ldmatrix.sync.aligned.m8n8.x4.shared.b16 {%0,%1,%2,%3}, [%4];"
                 : "=r"(r[0]), "=r"(r[1]), "=r"(r[2]), "=r"(r[3]) : "r"(addr));
}
__device__ __forceinline__ void ldmx2(uint32_t addr, uint32_t* r) {
    asm volatile("ldmatrix.sync.aligned.m8n8.x2.shared.b16 {%0,%1}, [%2];"
                 : "=r"(r[0]), "=r"(r[1]) : "r"(addr));
}
__device__ __forceinline__ void ldmx2t(uint32_t addr, uint32_t* r) {
    asm volatile("ldmatrix.sync.aligned.m8n8.x2.trans.shared.b16 {%0,%1}, [%2];"
                 : "=r"(r[0]), "=r"(r[1]) : "r"(addr));
}

__device__ __forceinline__ uint32_t pack2h(float a, float b) {
    __half2 h = __floats2half2_rn(a, b);
    return *(uint32_t*)&h;
}

// ---------------------------------------------------------------------------
// Fused conversion kernel: x, w_qkv, w_out -> fp16
// ---------------------------------------------------------------------------
#define NX4   (ROWS_TOT * E_DIM / 4)   // 1048576
#define NWQ4  (F3 * E_DIM / 4)         // 786432
#define NWO4  (E_DIM * E_DIM / 4)      // 262144

__global__ void convert_all(const float* __restrict__ x,
                            const float* __restrict__ wq,
                            const float* __restrict__ wo,
                            __half* __restrict__ xh,
                            __half* __restrict__ wqh,
                            __half* __restrict__ woh)
{
    int i = blockIdx.x * blockDim.x + threadIdx.x;
    const float* src;
    __half* dst;
    int j;
    if (i < NX4)                 { src = x;  dst = xh;  j = i; }
    else if (i < NX4 + NWQ4)     { src = wq; dst = wqh; j = i - NX4; }
    else                         { src = wo; dst = woh; j = i - NX4 - NWQ4; }
    float4 v = *(const float4*)(src + (size_t)j * 4);
    *(uint2*)(dst + (size_t)j * 4) =
        make_uint2(pack2h(v.x, v.y), pack2h(v.z, v.w));
}

// ---------------------------------------------------------------------------
// fp16 NT GEMM: C = A B^T (single term).
// 256(M)x128(N)x64 CTA tile, 512 threads (16 warps as 4Mx4N, warp 64x32),
// 3-stage cp.async pipeline, BK=64 to amortize barriers/loads.
// ---------------------------------------------------------------------------
#define BK    64
#define PADK  72                           // elems per smem row (144 bytes)
#define PADB  (PADK * 2)                   // 144-byte row stride
#define TILE_A_BYTES (256 * PADB)          // 36864
#define TILE_B_BYTES (128 * PADB)          // 18432
#define STAGE_BYTES  (TILE_A_BYTES + TILE_B_BYTES)       // 55296
#define GEMM_SMEM    (3 * STAGE_BYTES)     // 165888

__global__ __launch_bounds__(512, 1) void gemm_mma(
    const __half* __restrict__ Ah,
    const __half* __restrict__ Bh,
    float* __restrict__ C,
    __half* __restrict__ Ch,
    int split_out, int scale_cols, int M, int Nc, int K)
{
    extern __shared__ __align__(16) char smem[];
    const int tid  = threadIdx.x;
    const int lane = tid & 31;
    const int wid  = tid >> 5;
    const int bm = blockIdx.y * 256;
    const int bn = blockIdx.x * 128;
    const int wm = (wid >> 2) * 64;
    const int wn = (wid & 3) * 32;

    const __half* Ab = Ah + (size_t)bm * K;
    const __half* Bb = Bh + (size_t)bn * K;

    // Loader per stage: A = 2048 16B-chunks (4/thread), B = 1024 (2/thread)
    //   chunk ch: row = ch>>3, col = (ch&7)*8 halfs   (8 chunks per 64-h row)
    auto load_stage = [&](int stage, int c) {
        const int k0 = c * BK;
        char* st = smem + stage * STAGE_BYTES;
        #pragma unroll
        for (int it = 0; it < 4; it++) {
            const int ch = tid + it * 512;
            const int r = ch >> 3;
            const int cc = (ch & 7) * 8;
            cp_async16(smem_u32((__half*)st + r * PADK + cc),
                       Ab + (size_t)r * K + k0 + cc);
        }
        #pragma unroll
        for (int it = 0; it < 2; it++) {
            const int ch = tid + it * 512;
            const int r = ch >> 3;            // 0..127
            const int cc = (ch & 7) * 8;
            __half* dst = (__half*)(st + TILE_A_BYTES);
            cp_async16(smem_u32(dst + r * PADK + cc),
                       Bb + (size_t)r * K + k0 + cc);
        }
        CP_COMMIT();
    };

    float d[4][4][4];
    #pragma unroll
    for (int i = 0; i < 4; i++)
        #pragma unroll
        for (int j = 0; j < 4; j++)
            #pragma unroll
            for (int r = 0; r < 4; r++) d[i][j][r] = 0.0f;

    const int lr4 = lane >> 2;
    const int lk2 = (lane & 3) * 2;

    const uint32_t sbase = smem_u32(smem);
    const uint32_t a_off = (uint32_t)((wm + (lane & 15)) * PADB + ((lane >> 4) * 8) * 2);
    const uint32_t b_off = (uint32_t)((wn + (lane & 7)) * PADB + (((lane >> 3) & 1) * 8) * 2);

    const int nch = K / BK;                // >= 16 here
    load_stage(0, 0);
    load_stage(1, 1);

    for (int c = 0; c < nch; c++) {
        const int sg = c % 3;
        if (c + 1 < nch) { CP_WAIT(1); } else { CP_WAIT(0); }
        __syncthreads();
        if (c + 2 < nch) load_stage((c + 2) % 3, c + 2);

        const uint32_t sA = sbase + (uint32_t)(sg * STAGE_BYTES);
        const uint32_t sB = sA + TILE_A_BYTES;

        #pragma unroll
        for (int s = 0; s < 4; s++) {       // 4 k16 steps per 64-chunk
            const uint32_t kof = (uint32_t)(s * 32);
            uint32_t af[4][4];
            #pragma unroll
            for (int i = 0; i < 4; i++)
                ldmx4(sA + a_off + (uint32_t)(i * 16 * PADB) + kof, af[i]);
            #pragma unroll
            for (int j = 0; j < 4; j++) {
                uint32_t bf[2];
                ldmx2(sB + b_off + (uint32_t)(j * 8 * PADB) + kof, bf);
                #pragma unroll
                for (int i = 0; i < 4; i++) mma16816h(d[i][j], af[i], bf);
            }
        }
    }

    if (split_out) {
        #pragma unroll
        for (int i = 0; i < 4; i++) {
            const int row = bm + wm + i * 16 + lr4;
            #pragma unroll
            for (int j = 0; j < 4; j++) {
                const int col = bn + wn + j * 8 + lk2;
                const float sc = (col < scale_cols) ? SCALE_F : 1.0f;
                *(uint32_t*)(Ch + (size_t)row * Nc + col) =
                    pack2h(d[i][j][0] * sc, d[i][j][1] * sc);
                *(uint32_t*)(Ch + (size_t)(row + 8) * Nc + col) =
                    pack2h(d[i][j][2] * sc, d[i][j][3] * sc);
            }
        }
    } else {
        #pragma unroll
        for (int i = 0; i < 4; i++) {
            const int row = bm + wm + i * 16 + lr4;
            #pragma unroll
            for (int j = 0; j < 4; j++) {
                const int col = bn + wn + j * 8 + lk2;
                *(float2*)(C + (size_t)row * Nc + col) =
                    make_float2(d[i][j][0], d[i][j][1]);
                *(float2*)(C + (size_t)(row + 8) * Nc + col) =
                    make_float2(d[i][j][2], d[i][j][3]);
            }
        }
    }
}

// ---------------------------------------------------------------------------
// Flash attention, pure fp16, causal, 2-stage cp.async K/V prefetch.
// (unchanged from R13 — validated at 5.22e-4)
// ---------------------------------------------------------------------------
#define FPAD 72
#define FTILE (64 * FPAD)                  // halfs per K or V tile
#define FBUF_BYTES (2 * FTILE * 2)         // Kh,Vh = 18432
#define FLASH_SMEM (2 * FBUF_BYTES)        // 36864

__global__ __launch_bounds__(256) void flash_mma(
    const __half* __restrict__ qkvh,
    __half* __restrict__ ah)
{
    extern __shared__ __align__(16) char fsm[];

    const int tid  = threadIdx.x;
    const int lane = tid & 31;
    const int w    = tid >> 5;
    const int qi   = (int)gridDim.x - 1 - (int)blockIdx.x;
    const int by   = blockIdx.y;
    const int n    = by >> 4;
    const int h    = by & 15;
    const int q0   = qi * 128;
    const int lr4  = lane >> 2;
    const int lk2  = (lane & 3) * 2;

    const __half* qhp = qkvh + (size_t)n * F3 + h * D_HEAD;
    const __half* khp = qhp + E_DIM;
    const __half* vhp = qhp + 2 * E_DIM;

    // ---- Phase 1: stage Q in buffer 0, build fragments ----
    {
        __half* Qsh = (__half*)fsm;
        #pragma unroll
        for (int i = 0; i < 4; i++) {
            int ch = tid + i * 256;
            int r  = ch >> 3;
            int c  = (ch & 7) * 8;
            *(uint4*)&Qsh[r * FPAD + c] =
                *(const uint4*)(qhp + (size_t)(q0 + r) * QKV_ROW + c);
        }
    }
    __syncthreads();

    uint32_t qh[4][4];
    {
        const uint32_t qa = (uint32_t)(((w * 16 + (lane & 15)) * FPAD +
                                        (lane >> 4) * 8) * 2);
        const uint32_t sQh = smem_u32(fsm);
        #pragma unroll
        for (int st = 0; st < 4; st++)
            ldmx4(sQh + qa + st * 32, qh[st]);
    }
    __syncthreads();

    const __half* fsrc[2] = {khp, vhp};
    auto load_tile = [&](int buf, int kt) {
        char* base = fsm + buf * FBUF_BYTES;
        #pragma unroll
        for (int i = 0; i < 4; i++) {
            int ch = tid + i * 256;
            int t  = ch >> 9;
            int rr = (ch >> 3) & 63;
            int cc = (ch & 7) * 8;
            __half* dst = (__half*)base + t * FTILE + rr * FPAD + cc;
            cp_async16(smem_u32(dst),
                       fsrc[t] + (size_t)(kt * 64 + rr) * QKV_ROW + cc);
        }
        CP_COMMIT();
    };

    float rm0 = -1e30f, rm1 = -1e30f, rl0 = 0.0f, rl1 = 0.0f;
    float o[8][4];
    #pragma unroll
    for (int j = 0; j < 8; j++)
        #pragma unroll
        for (int r = 0; r < 4; r++) o[j][r] = 0.0f;

    const int nkt = 2 * qi + 2;
    load_tile(0, 0);

    for (int kt = 0; kt < nkt; kt++) {
        const int b = kt & 1;
        CP_WAIT(0);
        __syncthreads();
        if (kt + 1 < nkt) load_tile(b ^ 1, kt + 1);

        const __half* Kh = (const __half*)(fsm + b * FBUF_BYTES);
        const __half* Vh = Kh + FTILE;

        float s[8][4];
        #pragma unroll
        for (int j = 0; j < 8; j++)
            #pragma unroll
            for (int r = 0; r < 4; r++) s[j][r] = 0.0f;

        #pragma unroll
        for (int st = 0; st < 4; st++) {
            const int kb = st * 16 + lk2;
            #pragma unroll
            for (int jp = 0; jp < 4; jp++) {
                const int n0 = (2 * jp)     * 8 + lr4;
                const int n1 = (2 * jp + 1) * 8 + lr4;
                uint32_t bh0[2], bh1[2];
                bh0[0] = *(const uint32_t*)(Kh + n0 * FPAD + kb);
                bh0[1] = *(const uint32_t*)(Kh + n0 * FPAD + kb + 8);
                bh1[0] = *(const uint32_t*)(Kh + n1 * FPAD + kb);
                bh1[1] = *(const uint32_t*)(Kh + n1 * FPAD + kb + 8);
                mma16816h(s[2*jp],   qh[st], bh0);
                mma16816h(s[2*jp+1], qh[st], bh1);
            }
        }

        if (kt >= 2 * qi) {
            const int r0g = q0 + w * 16 + lr4;
            const int r1g = r0g + 8;
            #pragma unroll
            for (int j = 0; j < 8; j++) {
                const int cg = kt * 64 + j * 8 + lk2;
                if (cg     > r0g) s[j][0] = -1e30f;
                if (cg + 1 > r0g) s[j][1] = -1e30f;
                if (cg     > r1g) s[j][2] = -1e30f;
                if (cg + 1 > r1g) s[j][3] = -1e30f;
            }
        }

        float mx0 = -1e30f, mx1 = -1e30f;
        #pragma unroll
        for (int j = 0; j < 8; j++) {
            mx0 = fmaxf(mx0, fmaxf(s[j][0], s[j][1]));
            mx1 = fmaxf(mx1, fmaxf(s[j][2], s[j][3]));
        }
        mx0 = fmaxf(mx0, __shfl_xor_sync(0xffffffffu, mx0, 1));
        mx0 = fmaxf(mx0, __shfl_xor_sync(0xffffffffu, mx0, 2));
        mx1 = fmaxf(mx1, __shfl_xor_sync(0xffffffffu, mx1, 1));
        mx1 = fmaxf(mx1, __shfl_xor_sync(0xffffffffu, mx1, 2));

        const float mn0 = fmaxf(rm0, mx0);
        const float mn1 = fmaxf(rm1, mx1);
        const float a0 = __expf(rm0 - mn0);
        const float a1 = __expf(rm1 - mn1);
        rm0 = mn0; rm1 = mn1;

        float sum0 = 0.0f, sum1 = 0.0f;
        #pragma unroll
        for (int j = 0; j < 8; j++) {
            s[j][0] = __expf(s[j][0] - mn0);
            s[j][1] = __expf(s[j][1] - mn0);
            s[j][2] = __expf(s[j][2] - mn1);
            s[j][3] = __expf(s[j][3] - mn1);
            sum0 += s[j][0] + s[j][1];
            sum1 += s[j][2] + s[j][3];
        }
        sum0 += __shfl_xor_sync(0xffffffffu, sum0, 1);
        sum0 += __shfl_xor_sync(0xffffffffu, sum0, 2);
        sum1 += __shfl_xor_sync(0xffffffffu, sum1, 1);
        sum1 += __shfl_xor_sync(0xffffffffu, sum1, 2);
        rl0 = rl0 * a0 + sum0;
        rl1 = rl1 * a1 + sum1;

        #pragma unroll
        for (int j = 0; j < 8; j++) {
            o[j][0] *= a0; o[j][1] *= a0;
            o[j][2] *= a1; o[j][3] *= a1;
        }

        #pragma unroll
        for (int st = 0; st < 4; st++) {
            uint32_t pah[4];
            pah[0] = pack2h(s[2*st][0],   s[2*st][1]);
            pah[1] = pack2h(s[2*st][2],   s[2*st][3]);
            pah[2] = pack2h(s[2*st+1][0], s[2*st+1][1]);
            pah[3] = pack2h(s[2*st+1][2], s[2*st+1][3]);
            const int vrow = st * 16 + (lane & 15);
            #pragma unroll
            for (int jp = 0; jp < 4; jp++) {
                const int j0 = 2 * jp, j1 = 2 * jp + 1;
                uint32_t bh0[2], bh1[2];
                ldmx2t(smem_u32(Vh + vrow * FPAD + j0 * 8), bh0);
                ldmx2t(smem_u32(Vh + vrow * FPAD + j1 * 8), bh1);
                mma16816h(o[j0], pah, bh0);
                mma16816h(o[j1], pah, bh1);
            }
        }
    }

    const float inv0 = 1.0f / rl0;
    const float inv1 = 1.0f / rl1;
    const int r0g = q0 + w * 16 + lr4;
    const size_t row0 = (size_t)(r0g * N_BATCH + n) * E_DIM;
    const size_t row1 = (size_t)((r0g + 8) * N_BATCH + n) * E_DIM;
    #pragma unroll
    for (int j = 0; j < 8; j++) {
        const int col = h * D_HEAD + j * 8 + lk2;
        *(uint32_t*)(ah + row0 + col) = pack2h(o[j][0] * inv0, o[j][1] * inv0);
        *(uint32_t*)(ah + row1 + col) = pack2h(o[j][2] * inv1, o[j][3] * inv1);
    }
}

// ---------------------------------------------------------------------------
extern "C" void kernel_launch(void* const* d_in, const int* in_sizes, int n_in,
                              void* d_out, int out_size)
{
    const float* x     = (const float*)d_in[0];
    const float* w_qkv = (const float*)d_in[1];
    const float* w_out = (const float*)d_in[2];
    float* out = (float*)d_out;

    __half *qkvh, *xh, *wqh, *woh, *ah;
    cudaGetSymbolAddress((void**)&qkvh, g_qkvh);
    cudaGetSymbolAddress((void**)&xh,   g_xh);
    cudaGetSymbolAddress((void**)&wqh,  g_wqh);
    cudaGetSymbolAddress((void**)&woh,  g_woh);
    cudaGetSymbolAddress((void**)&ah,   g_ah);

    cudaFuncSetAttribute(gemm_mma,
                         cudaFuncAttributeMaxDynamicSharedMemorySize, GEMM_SMEM);
    cudaFuncSetAttribute(flash_mma,
                         cudaFuncAttributeMaxDynamicSharedMemorySize, FLASH_SMEM);

    // 0) fused conversions
    {
        int total = NX4 + NWQ4 + NWO4;
        convert_all<<<(total + 255) / 256, 256>>>(x, w_qkv, w_out, xh, wqh, woh);
    }

    // 1) QKV projection -> fp16 (Q region scaled by 1/8)
    gemm_mma<<<dim3(F3 / 128, ROWS_TOT / 256), 512, GEMM_SMEM>>>(
        xh, wqh, nullptr, qkvh, 1, E_DIM, ROWS_TOT, F3, E_DIM);

    // 2) Causal flash attention -> fp16
    flash_mma<<<dim3(L_SEQ / 128, N_BATCH * H_HEADS), 256, FLASH_SMEM>>>(
        qkvh, ah);

    // 3) Output projection -> fp32 out
    gemm_mma<<<dim3(E_DIM / 128, ROWS_TOT / 256), 512, GEMM_SMEM>>>(
        ah, woh, out, nullptr, 0, 0, ROWS_TOT, E_DIM, E_DIM);
}

// round 15
// speedup vs baseline: 1.7156x; 1.0557x over previous
#include <cuda_runtime.h>
#include <cuda_fp16.h>
#include <cstdint>
#include <cstddef>

// Problem constants
#define L_SEQ   2048
#define N_BATCH 2
#define E_DIM   1024
#define H_HEADS 16
#define D_HEAD  64
#define SCALE_F 0.125f
#define LOG2E_F 1.4426950408889634f
#define ROWS_TOT (L_SEQ * N_BATCH)     // 4096
#define F3       (3 * E_DIM)           // 3072
#define QKV_ROW  (N_BATCH * F3)        // 6144

// ---------------------------------------------------------------------------
// Scratch (no cudaMalloc allowed)
// ---------------------------------------------------------------------------
__device__ __half g_qkvh[(size_t)ROWS_TOT * F3];   // qkv fp16 (Q pre-scaled)
__device__ __half g_xh [(size_t)ROWS_TOT * E_DIM];
__device__ __half g_wqh[(size_t)F3 * E_DIM];
__device__ __half g_woh[(size_t)E_DIM * E_DIM];
__device__ __half g_ah [(size_t)ROWS_TOT * E_DIM]; // attention out fp16

// ---------------------------------------------------------------------------
// Helpers
// ---------------------------------------------------------------------------
__device__ __forceinline__ uint32_t smem_u32(const void* p) {
    uint32_t a;
    asm("{ .reg .u64 t; cvta.to.shared.u64 t, %1; cvt.u32.u64 %0, t; }"
        : "=r"(a) : "l"(p));
    return a;
}

__device__ __forceinline__ void cp_async16(uint32_t dst, const void* src) {
    asm volatile("cp.async.cg.shared.global [%0], [%1], 16;"
                 :: "r"(dst), "l"(src) : "memory");
}
#define CP_COMMIT()  asm volatile("cp.async.commit_group;" ::: "memory")
#define CP_WAIT(n)   asm volatile("cp.async.wait_group %0;" :: "n"(n) : "memory")

// fp16 m16n8k16 MMA, fp32 accumulate
__device__ __forceinline__ void mma16816h(float* d, const uint32_t* a,
                                          const uint32_t* b) {
    asm volatile(
        "mma.sync.aligned.m16n8k16.row.col.f32.f16.f16.f32 "
        "{%0,%1,%2,%3}, {%4,%5,%6,%7}, {%8,%9}, {%0,%1,%2,%3};"
        : "+f"(d[0]), "+f"(d[1]), "+f"(d[2]), "+f"(d[3])
        : "r"(a[0]), "r"(a[1]), "r"(a[2]), "r"(a[3]), "r"(b[0]), "r"(b[1]));
}

__device__ __forceinline__ void ldmx4(uint32_t addr, uint32_t* r) {
    asm volatile("ldmatrix.sync.aligned.m8n8.x4.shared.b16 {%0,%1,%2,%3}, [%4];"
                 : "=r"(r[0]), "=r"(r[1]), "=r"(r[2]), "=r"(r[3]) : "r"(addr));
}
__device__ __forceinline__ void ldmx2(uint32_t addr, uint32_t* r) {
    asm volatile("ldmatrix.sync.aligned.m8n8.x2.shared.b16 {%0,%1}, [%2];"
                 : "=r"(r[0]), "=r"(r[1]) : "r"(addr));
}
__device__ __forceinline__ void ldmx2t(uint32_t addr, uint32_t* r) {
    asm volatile("ldmatrix.sync.aligned.m8n8.x2.trans.shared.b16 {%0,%1}, [%2];"
                 : "=r"(r[0]), "=r"(r[1]) : "r"(addr));
}

__device__ __forceinline__ uint32_t pack2h(float a, float b) {
    __half2 h = __floats2half2_rn(a, b);
    return *(uint32_t*)&h;
}

// two fp16 exp2 per MUFU op
__device__ __forceinline__ uint32_t h2exp2u(uint32_t x) {
    uint32_t r;
    asm("ex2.approx.f16x2 %0, %1;" : "=r"(r) : "r"(x));
    return r;
}

// ---------------------------------------------------------------------------
// Fused conversion kernel: x, w_qkv, w_out -> fp16
// ---------------------------------------------------------------------------
#define NX4   (ROWS_TOT * E_DIM / 4)   // 1048576
#define NWQ4  (F3 * E_DIM / 4)         // 786432
#define NWO4  (E_DIM * E_DIM / 4)      // 262144

__global__ void convert_all(const float* __restrict__ x,
                            const float* __restrict__ wq,
                            const float* __restrict__ wo,
                            __half* __restrict__ xh,
                            __half* __restrict__ wqh,
                            __half* __restrict__ woh)
{
    int i = blockIdx.x * blockDim.x + threadIdx.x;
    const float* src;
    __half* dst;
    int j;
    if (i < NX4)                 { src = x;  dst = xh;  j = i; }
    else if (i < NX4 + NWQ4)     { src = wq; dst = wqh; j = i - NX4; }
    else                         { src = wo; dst = woh; j = i - NX4 - NWQ4; }
    float4 v = *(const float4*)(src + (size_t)j * 4);
    *(uint2*)(dst + (size_t)j * 4) =
        make_uint2(pack2h(v.x, v.y), pack2h(v.z, v.w));
}

// ---------------------------------------------------------------------------
// fp16 NT GEMM: C = A B^T.  256x128x64 CTA tile, 512 threads, 3-stage.
// (unchanged from R14 — validated)
// ---------------------------------------------------------------------------
#define BK    64
#define PADK  72
#define PADB  (PADK * 2)                   // 144-byte row stride
#define TILE_A_BYTES (256 * PADB)          // 36864
#define TILE_B_BYTES (128 * PADB)          // 18432
#define STAGE_BYTES  (TILE_A_BYTES + TILE_B_BYTES)       // 55296
#define GEMM_SMEM    (3 * STAGE_BYTES)     // 165888

__global__ __launch_bounds__(512, 1) void gemm_mma(
    const __half* __restrict__ Ah,
    const __half* __restrict__ Bh,
    float* __restrict__ C,
    __half* __restrict__ Ch,
    int split_out, int scale_cols, int M, int Nc, int K)
{
    extern __shared__ __align__(16) char smem[];
    const int tid  = threadIdx.x;
    const int lane = tid & 31;
    const int wid  = tid >> 5;
    const int bm = blockIdx.y * 256;
    const int bn = blockIdx.x * 128;
    const int wm = (wid >> 2) * 64;
    const int wn = (wid & 3) * 32;

    const __half* Ab = Ah + (size_t)bm * K;
    const __half* Bb = Bh + (size_t)bn * K;

    auto load_stage = [&](int stage, int c) {
        const int k0 = c * BK;
        char* st = smem + stage * STAGE_BYTES;
        #pragma unroll
        for (int it = 0; it < 4; it++) {
            const int ch = tid + it * 512;
            const int r = ch >> 3;
            const int cc = (ch & 7) * 8;
            cp_async16(smem_u32((__half*)st + r * PADK + cc),
                       Ab + (size_t)r * K + k0 + cc);
        }
        #pragma unroll
        for (int it = 0; it < 2; it++) {
            const int ch = tid + it * 512;
            const int r = ch >> 3;
            const int cc = (ch & 7) * 8;
            __half* dst = (__half*)(st + TILE_A_BYTES);
            cp_async16(smem_u32(dst + r * PADK + cc),
                       Bb + (size_t)r * K + k0 + cc);
        }
        CP_COMMIT();
    };

    float d[4][4][4];
    #pragma unroll
    for (int i = 0; i < 4; i++)
        #pragma unroll
        for (int j = 0; j < 4; j++)
            #pragma unroll
            for (int r = 0; r < 4; r++) d[i][j][r] = 0.0f;

    const int lr4 = lane >> 2;
    const int lk2 = (lane & 3) * 2;

    const uint32_t sbase = smem_u32(smem);
    const uint32_t a_off = (uint32_t)((wm + (lane & 15)) * PADB + ((lane >> 4) * 8) * 2);
    const uint32_t b_off = (uint32_t)((wn + (lane & 7)) * PADB + (((lane >> 3) & 1) * 8) * 2);

    const int nch = K / BK;
    load_stage(0, 0);
    load_stage(1, 1);

    for (int c = 0; c < nch; c++) {
        const int sg = c % 3;
        if (c + 1 < nch) { CP_WAIT(1); } else { CP_WAIT(0); }
        __syncthreads();
        if (c + 2 < nch) load_stage((c + 2) % 3, c + 2);

        const uint32_t sA = sbase + (uint32_t)(sg * STAGE_BYTES);
        const uint32_t sB = sA + TILE_A_BYTES;

        #pragma unroll
        for (int s = 0; s < 4; s++) {
            const uint32_t kof = (uint32_t)(s * 32);
            uint32_t af[4][4];
            #pragma unroll
            for (int i = 0; i < 4; i++)
                ldmx4(sA + a_off + (uint32_t)(i * 16 * PADB) + kof, af[i]);
            #pragma unroll
            for (int j = 0; j < 4; j++) {
                uint32_t bf[2];
                ldmx2(sB + b_off + (uint32_t)(j * 8 * PADB) + kof, bf);
                #pragma unroll
                for (int i = 0; i < 4; i++) mma16816h(d[i][j], af[i], bf);
            }
        }
    }

    if (split_out) {
        #pragma unroll
        for (int i = 0; i < 4; i++) {
            const int row = bm + wm + i * 16 + lr4;
            #pragma unroll
            for (int j = 0; j < 4; j++) {
                const int col = bn + wn + j * 8 + lk2;
                const float sc = (col < scale_cols) ? SCALE_F : 1.0f;
                *(uint32_t*)(Ch + (size_t)row * Nc + col) =
                    pack2h(d[i][j][0] * sc, d[i][j][1] * sc);
                *(uint32_t*)(Ch + (size_t)(row + 8) * Nc + col) =
                    pack2h(d[i][j][2] * sc, d[i][j][3] * sc);
            }
        }
    } else {
        #pragma unroll
        for (int i = 0; i < 4; i++) {
            const int row = bm + wm + i * 16 + lr4;
            #pragma unroll
            for (int j = 0; j < 4; j++) {
                const int col = bn + wn + j * 8 + lk2;
                *(float2*)(C + (size_t)row * Nc + col) =
                    make_float2(d[i][j][0], d[i][j][1]);
                *(float2*)(C + (size_t)(row + 8) * Nc + col) =
                    make_float2(d[i][j][2], d[i][j][3]);
            }
        }
    }
}

// ---------------------------------------------------------------------------
// Flash attention, pure fp16, causal, 2-stage cp.async K/V prefetch.
// Softmax P computed with ex2.approx.f16x2 (2 exps per MUFU op).
// ---------------------------------------------------------------------------
#define FPAD 72
#define FTILE (64 * FPAD)
#define FBUF_BYTES (2 * FTILE * 2)         // Kh,Vh = 18432
#define FLASH_SMEM (2 * FBUF_BYTES)        // 36864

__global__ __launch_bounds__(256) void flash_mma(
    const __half* __restrict__ qkvh,
    __half* __restrict__ ah)
{
    extern __shared__ __align__(16) char fsm[];

    const int tid  = threadIdx.x;
    const int lane = tid & 31;
    const int w    = tid >> 5;
    const int qi   = (int)gridDim.x - 1 - (int)blockIdx.x;
    const int by   = blockIdx.y;
    const int n    = by >> 4;
    const int h    = by & 15;
    const int q0   = qi * 128;
    const int lr4  = lane >> 2;
    const int lk2  = (lane & 3) * 2;

    const __half* qhp = qkvh + (size_t)n * F3 + h * D_HEAD;
    const __half* khp = qhp + E_DIM;
    const __half* vhp = qhp + 2 * E_DIM;

    // ---- Phase 1: stage Q, build fragments ----
    {
        __half* Qsh = (__half*)fsm;
        #pragma unroll
        for (int i = 0; i < 4; i++) {
            int ch = tid + i * 256;
            int r  = ch >> 3;
            int c  = (ch & 7) * 8;
            *(uint4*)&Qsh[r * FPAD + c] =
                *(const uint4*)(qhp + (size_t)(q0 + r) * QKV_ROW + c);
        }
    }
    __syncthreads();

    uint32_t qh[4][4];
    {
        const uint32_t qa = (uint32_t)(((w * 16 + (lane & 15)) * FPAD +
                                        (lane >> 4) * 8) * 2);
        const uint32_t sQh = smem_u32(fsm);
        #pragma unroll
        for (int st = 0; st < 4; st++)
            ldmx4(sQh + qa + st * 32, qh[st]);
    }
    __syncthreads();

    const __half* fsrc[2] = {khp, vhp};
    auto load_tile = [&](int buf, int kt) {
        char* base = fsm + buf * FBUF_BYTES;
        #pragma unroll
        for (int i = 0; i < 4; i++) {
            int ch = tid + i * 256;
            int t  = ch >> 9;
            int rr = (ch >> 3) & 63;
            int cc = (ch & 7) * 8;
            __half* dst = (__half*)base + t * FTILE + rr * FPAD + cc;
            cp_async16(smem_u32(dst),
                       fsrc[t] + (size_t)(kt * 64 + rr) * QKV_ROW + cc);
        }
        CP_COMMIT();
    };

    float rm0 = -1e30f, rm1 = -1e30f, rl0 = 0.0f, rl1 = 0.0f;
    float o[8][4];
    #pragma unroll
    for (int j = 0; j < 8; j++)
        #pragma unroll
        for (int r = 0; r < 4; r++) o[j][r] = 0.0f;

    const int nkt = 2 * qi + 2;
    load_tile(0, 0);

    for (int kt = 0; kt < nkt; kt++) {
        const int b = kt & 1;
        CP_WAIT(0);
        __syncthreads();
        if (kt + 1 < nkt) load_tile(b ^ 1, kt + 1);

        const __half* Kh = (const __half*)(fsm + b * FBUF_BYTES);
        const __half* Vh = Kh + FTILE;

        // ---- S = Q K^T ----
        float s[8][4];
        #pragma unroll
        for (int j = 0; j < 8; j++)
            #pragma unroll
            for (int r = 0; r < 4; r++) s[j][r] = 0.0f;

        #pragma unroll
        for (int st = 0; st < 4; st++) {
            const int kb = st * 16 + lk2;
            #pragma unroll
            for (int jp = 0; jp < 4; jp++) {
                const int n0 = (2 * jp)     * 8 + lr4;
                const int n1 = (2 * jp + 1) * 8 + lr4;
                uint32_t bh0[2], bh1[2];
                bh0[0] = *(const uint32_t*)(Kh + n0 * FPAD + kb);
                bh0[1] = *(const uint32_t*)(Kh + n0 * FPAD + kb + 8);
                bh1[0] = *(const uint32_t*)(Kh + n1 * FPAD + kb);
                bh1[1] = *(const uint32_t*)(Kh + n1 * FPAD + kb + 8);
                mma16816h(s[2*jp],   qh[st], bh0);
                mma16816h(s[2*jp+1], qh[st], bh1);
            }
        }

        // ---- causal mask ----
        if (kt >= 2 * qi) {
            const int r0g = q0 + w * 16 + lr4;
            const int r1g = r0g + 8;
            #pragma unroll
            for (int j = 0; j < 8; j++) {
                const int cg = kt * 64 + j * 8 + lk2;
                if (cg     > r0g) s[j][0] = -1e30f;
                if (cg + 1 > r0g) s[j][1] = -1e30f;
                if (cg     > r1g) s[j][2] = -1e30f;
                if (cg + 1 > r1g) s[j][3] = -1e30f;
            }
        }

        // ---- online softmax (row max in fp32) ----
        float mx0 = -1e30f, mx1 = -1e30f;
        #pragma unroll
        for (int j = 0; j < 8; j++) {
            mx0 = fmaxf(mx0, fmaxf(s[j][0], s[j][1]));
            mx1 = fmaxf(mx1, fmaxf(s[j][2], s[j][3]));
        }
        mx0 = fmaxf(mx0, __shfl_xor_sync(0xffffffffu, mx0, 1));
        mx0 = fmaxf(mx0, __shfl_xor_sync(0xffffffffu, mx0, 2));
        mx1 = fmaxf(mx1, __shfl_xor_sync(0xffffffffu, mx1, 1));
        mx1 = fmaxf(mx1, __shfl_xor_sync(0xffffffffu, mx1, 2));

        const float mn0 = fmaxf(rm0, mx0);
        const float mn1 = fmaxf(rm1, mx1);
        const float a0 = __expf(rm0 - mn0);
        const float a1 = __expf(rm1 - mn1);
        rm0 = mn0; rm1 = mn1;

        // ---- P = exp(S - m) via ex2.approx.f16x2 (P stays fp16) ----
        uint32_t p[8][2];
        float sum0 = 0.0f, sum1 = 0.0f;
        #pragma unroll
        for (int j = 0; j < 8; j++) {
            __half2 e0 = __floats2half2_rn((s[j][0] - mn0) * LOG2E_F,
                                           (s[j][1] - mn0) * LOG2E_F);
            __half2 e1 = __floats2half2_rn((s[j][2] - mn1) * LOG2E_F,
                                           (s[j][3] - mn1) * LOG2E_F);
            p[j][0] = h2exp2u(*(uint32_t*)&e0);
            p[j][1] = h2exp2u(*(uint32_t*)&e1);
            float2 f0 = __half22float2(*(__half2*)&p[j][0]);
            float2 f1 = __half22float2(*(__half2*)&p[j][1]);
            sum0 += f0.x + f0.y;
            sum1 += f1.x + f1.y;
        }
        sum0 += __shfl_xor_sync(0xffffffffu, sum0, 1);
        sum0 += __shfl_xor_sync(0xffffffffu, sum0, 2);
        sum1 += __shfl_xor_sync(0xffffffffu, sum1, 1);
        sum1 += __shfl_xor_sync(0xffffffffu, sum1, 2);
        rl0 = rl0 * a0 + sum0;
        rl1 = rl1 * a1 + sum1;

        #pragma unroll
        for (int j = 0; j < 8; j++) {
            o[j][0] *= a0; o[j][1] *= a0;
            o[j][2] *= a1; o[j][3] *= a1;
        }

        // ---- O += P V (P fragments come straight from p[][]) ----
        #pragma unroll
        for (int st = 0; st < 4; st++) {
            uint32_t pah[4];
            pah[0] = p[2*st][0];
            pah[1] = p[2*st][1];
            pah[2] = p[2*st+1][0];
            pah[3] = p[2*st+1][1];
            const int vrow = st * 16 + (lane & 15);
            #pragma unroll
            for (int jp = 0; jp < 4; jp++) {
                const int j0 = 2 * jp, j1 = 2 * jp + 1;
                uint32_t bh0[2], bh1[2];
                ldmx2t(smem_u32(Vh + vrow * FPAD + j0 * 8), bh0);
                ldmx2t(smem_u32(Vh + vrow * FPAD + j1 * 8), bh1);
                mma16816h(o[j0], pah, bh0);
                mma16816h(o[j1], pah, bh1);
            }
        }
    }

    // ---- epilogue: normalize, write fp16 ----
    const float inv0 = 1.0f / rl0;
    const float inv1 = 1.0f / rl1;
    const int r0g = q0 + w * 16 + lr4;
    const size_t row0 = (size_t)(r0g * N_BATCH + n) * E_DIM;
    const size_t row1 = (size_t)((r0g + 8) * N_BATCH + n) * E_DIM;
    #pragma unroll
    for (int j = 0; j < 8; j++) {
        const int col = h * D_HEAD + j * 8 + lk2;
        *(uint32_t*)(ah + row0 + col) = pack2h(o[j][0] * inv0, o[j][1] * inv0);
        *(uint32_t*)(ah + row1 + col) = pack2h(o[j][2] * inv1, o[j][3] * inv1);
    }
}

// ---------------------------------------------------------------------------
extern "C" void kernel_launch(void* const* d_in, const int* in_sizes, int n_in,
                              void* d_out, int out_size)
{
    const float* x     = (const float*)d_in[0];
    const float* w_qkv = (const float*)d_in[1];
    const float* w_out = (const float*)d_in[2];
    float* out = (float*)d_out;

    __half *qkvh, *xh, *wqh, *woh, *ah;
    cudaGetSymbolAddress((void**)&qkvh, g_qkvh);
    cudaGetSymbolAddress((void**)&xh,   g_xh);
    cudaGetSymbolAddress((void**)&wqh,  g_wqh);
    cudaGetSymbolAddress((void**)&woh,  g_woh);
    cudaGetSymbolAddress((void**)&ah,   g_ah);

    cudaFuncSetAttribute(gemm_mma,
                         cudaFuncAttributeMaxDynamicSharedMemorySize, GEMM_SMEM);
    cudaFuncSetAttribute(flash_mma,
                         cudaFuncAttributeMaxDynamicSharedMemorySize, FLASH_SMEM);

    // 0) fused conversions
    {
        int total = NX4 + NWQ4 + NWO4;
        convert_all<<<(total + 255) / 256, 256>>>(x, w_qkv, w_out, xh, wqh, woh);
    }

    // 1) QKV projection -> fp16 (Q region scaled by 1/8)
    gemm_mma<<<dim3(F3 / 128, ROWS_TOT / 256), 512, GEMM_SMEM>>>(
        xh, wqh, nullptr, qkvh, 1, E_DIM, ROWS_TOT, F3, E_DIM);

    // 2) Causal flash attention -> fp16
    flash_mma<<<dim3(L_SEQ / 128, N_BATCH * H_HEADS), 256, FLASH_SMEM>>>(
        qkvh, ah);

    // 3) Output projection -> fp32 out
    gemm_mma<<<dim3(E_DIM / 128, ROWS_TOT / 256), 512, GEMM_SMEM>>>(
        ah, woh, out, nullptr, 0, 0, ROWS_TOT, E_DIM, E_DIM);
}

// round 16
// speedup vs baseline: 1.7943x; 1.0459x over previous
#include <cuda_runtime.h>
#include <cuda_fp16.h>
#include <cstdint>
#include <cstddef>

// Problem constants
#define L_SEQ   2048
#define N_BATCH 2
#define E_DIM   1024
#define H_HEADS 16
#define D_HEAD  64
#define SCALE_F 0.125f
#define LOG2E_F 1.4426950408889634f
#define ROWS_TOT (L_SEQ * N_BATCH)     // 4096
#define F3       (3 * E_DIM)           // 3072
#define QKV_ROW  (N_BATCH * F3)        // 6144

// ---------------------------------------------------------------------------
// Scratch (no cudaMalloc allowed)
// ---------------------------------------------------------------------------
__device__ __half g_qkvh[(size_t)ROWS_TOT * F3];   // qkv fp16 (Q pre-scaled)
__device__ __half g_xh [(size_t)ROWS_TOT * E_DIM];
__device__ __half g_wqh[(size_t)F3 * E_DIM];
__device__ __half g_woh[(size_t)E_DIM * E_DIM];
__device__ __half g_ah [(size_t)ROWS_TOT * E_DIM]; // attention out fp16

// ---------------------------------------------------------------------------
// Helpers
// ---------------------------------------------------------------------------
__device__ __forceinline__ uint32_t smem_u32(const void* p) {
    uint32_t a;
    asm("{ .reg .u64 t; cvta.to.shared.u64 t, %1; cvt.u32.u64 %0, t; }"
        : "=r"(a) : "l"(p));
    return a;
}

__device__ __forceinline__ void cp_async16(uint32_t dst, const void* src) {
    asm volatile("cp.async.cg.shared.global [%0], [%1], 16;"
                 :: "r"(dst), "l"(src) : "memory");
}
#define CP_COMMIT()  asm volatile("cp.async.commit_group;" ::: "memory")
#define CP_WAIT(n)   asm volatile("cp.async.wait_group %0;" :: "n"(n) : "memory")

// fp16 m16n8k16 MMA, fp32 accumulate
__device__ __forceinline__ void mma16816h(float* d, const uint32_t* a,
                                          const uint32_t* b) {
    asm volatile(
        "mma.sync.aligned.m16n8k16.row.col.f32.f16.f16.f32 "
        "{%0,%1,%2,%3}, {%4,%5,%6,%7}, {%8,%9}, {%0,%1,%2,%3};"
        : "+f"(d[0]), "+f"(d[1]), "+f"(d[2]), "+f"(d[3])
        : "r"(a[0]), "r"(a[1]), "r"(a[2]), "r"(a[3]), "r"(b[0]), "r"(b[1]));
}

__device__ __forceinline__ void ldmx4(uint32_t addr, uint32_t* r) {
    asm volatile("ldmatrix.sync.aligned.m8n8.x4.shared.b16 {%0,%1,%2,%3}, [%4];"
                 : "=r"(r[0]), "=r"(r[1]), "=r"(r[2]), "=r"(r[3]) : "r"(addr));
}
__device__ __forceinline__ void ldmx2t(uint32_t addr, uint32_t* r) {
    asm volatile("ldmatrix.sync.aligned.m8n8.x2.trans.shared.b16 {%0,%1}, [%2];"
                 : "=r"(r[0]), "=r"(r[1]) : "r"(addr));
}

__device__ __forceinline__ uint32_t pack2h(float a, float b) {
    __half2 h = __floats2half2_rn(a, b);
    return *(uint32_t*)&h;
}

// two fp16 exp2 per MUFU op
__device__ __forceinline__ uint32_t h2exp2u(uint32_t x) {
    uint32_t r;
    asm("ex2.approx.f16x2 %0, %1;" : "=r"(r) : "r"(x));
    return r;
}

// ---------------------------------------------------------------------------
// Fused conversion kernel: x, w_qkv, w_out -> fp16
// ---------------------------------------------------------------------------
#define NX4   (ROWS_TOT * E_DIM / 4)   // 1048576
#define NWQ4  (F3 * E_DIM / 4)         // 786432
#define NWO4  (E_DIM * E_DIM / 4)      // 262144

__global__ void convert_all(const float* __restrict__ x,
                            const float* __restrict__ wq,
                            const float* __restrict__ wo,
                            __half* __restrict__ xh,
                            __half* __restrict__ wqh,
                            __half* __restrict__ woh)
{
    int i = blockIdx.x * blockDim.x + threadIdx.x;
    const float* src;
    __half* dst;
    int j;
    if (i < NX4)                 { src = x;  dst = xh;  j = i; }
    else if (i < NX4 + NWQ4)     { src = wq; dst = wqh; j = i - NX4; }
    else                         { src = wo; dst = woh; j = i - NX4 - NWQ4; }
    float4 v = *(const float4*)(src + (size_t)j * 4);
    *(uint2*)(dst + (size_t)j * 4) =
        make_uint2(pack2h(v.x, v.y), pack2h(v.z, v.w));
}

// ---------------------------------------------------------------------------
// fp16 NT GEMM: C = A B^T.  256x128x64 CTA tile, 512 threads, 3-stage.
// B fragments via ldmatrix.x4 (j-pair per op).
// ---------------------------------------------------------------------------
#define BK    64
#define PADK  72
#define PADB  (PADK * 2)                   // 144-byte row stride
#define TILE_A_BYTES (256 * PADB)          // 36864
#define TILE_B_BYTES (128 * PADB)          // 18432
#define STAGE_BYTES  (TILE_A_BYTES + TILE_B_BYTES)       // 55296
#define GEMM_SMEM    (3 * STAGE_BYTES)     // 165888

__global__ __launch_bounds__(512, 1) void gemm_mma(
    const __half* __restrict__ Ah,
    const __half* __restrict__ Bh,
    float* __restrict__ C,
    __half* __restrict__ Ch,
    int split_out, int scale_cols, int M, int Nc, int K)
{
    extern __shared__ __align__(16) char smem[];
    const int tid  = threadIdx.x;
    const int lane = tid & 31;
    const int wid  = tid >> 5;
    const int bm = blockIdx.y * 256;
    const int bn = blockIdx.x * 128;
    const int wm = (wid >> 2) * 64;
    const int wn = (wid & 3) * 32;

    const __half* Ab = Ah + (size_t)bm * K;
    const __half* Bb = Bh + (size_t)bn * K;

    auto load_stage = [&](int stage, int c) {
        const int k0 = c * BK;
        char* st = smem + stage * STAGE_BYTES;
        #pragma unroll
        for (int it = 0; it < 4; it++) {
            const int ch = tid + it * 512;
            const int r = ch >> 3;
            const int cc = (ch & 7) * 8;
            cp_async16(smem_u32((__half*)st + r * PADK + cc),
                       Ab + (size_t)r * K + k0 + cc);
        }
        #pragma unroll
        for (int it = 0; it < 2; it++) {
            const int ch = tid + it * 512;
            const int r = ch >> 3;
            const int cc = (ch & 7) * 8;
            __half* dst = (__half*)(st + TILE_A_BYTES);
            cp_async16(smem_u32(dst + r * PADK + cc),
                       Bb + (size_t)r * K + k0 + cc);
        }
        CP_COMMIT();
    };

    float d[4][4][4];
    #pragma unroll
    for (int i = 0; i < 4; i++)
        #pragma unroll
        for (int j = 0; j < 4; j++)
            #pragma unroll
            for (int r = 0; r < 4; r++) d[i][j][r] = 0.0f;

    const int lr4 = lane >> 2;
    const int lk2 = (lane & 3) * 2;

    const uint32_t sbase = smem_u32(smem);
    const uint32_t a_off  = (uint32_t)((wm + (lane & 15)) * PADB + ((lane >> 4) * 8) * 2);
    // x4 B addressing: lanes 0-7 rows n..n+7 col 0; 8-15 col+8; 16-23 rows n+8; 24-31 rows n+8 col+8
    const uint32_t b4_off = (uint32_t)((wn + (lane & 7) + ((lane >> 4) << 3)) * PADB
                                       + (((lane >> 3) & 1) * 8) * 2);

    const int nch = K / BK;
    load_stage(0, 0);
    load_stage(1, 1);

    for (int c = 0; c < nch; c++) {
        const int sg = c % 3;
        if (c + 1 < nch) { CP_WAIT(1); } else { CP_WAIT(0); }
        __syncthreads();
        if (c + 2 < nch) load_stage((c + 2) % 3, c + 2);

        const uint32_t sA = sbase + (uint32_t)(sg * STAGE_BYTES);
        const uint32_t sB = sA + TILE_A_BYTES;

        #pragma unroll
        for (int s = 0; s < 4; s++) {
            const uint32_t kof = (uint32_t)(s * 32);
            uint32_t af[4][4];
            #pragma unroll
            for (int i = 0; i < 4; i++)
                ldmx4(sA + a_off + (uint32_t)(i * 16 * PADB) + kof, af[i]);
            #pragma unroll
            for (int jp = 0; jp < 2; jp++) {
                uint32_t bf[4];
                ldmx4(sB + b4_off + (uint32_t)(jp * 16 * PADB) + kof, bf);
                #pragma unroll
                for (int i = 0; i < 4; i++) mma16816h(d[i][2*jp],   af[i], bf);
                #pragma unroll
                for (int i = 0; i < 4; i++) mma16816h(d[i][2*jp+1], af[i], bf + 2);
            }
        }
    }

    if (split_out) {
        #pragma unroll
        for (int i = 0; i < 4; i++) {
            const int row = bm + wm + i * 16 + lr4;
            #pragma unroll
            for (int j = 0; j < 4; j++) {
                const int col = bn + wn + j * 8 + lk2;
                const float sc = (col < scale_cols) ? SCALE_F : 1.0f;
                *(uint32_t*)(Ch + (size_t)row * Nc + col) =
                    pack2h(d[i][j][0] * sc, d[i][j][1] * sc);
                *(uint32_t*)(Ch + (size_t)(row + 8) * Nc + col) =
                    pack2h(d[i][j][2] * sc, d[i][j][3] * sc);
            }
        }
    } else {
        #pragma unroll
        for (int i = 0; i < 4; i++) {
            const int row = bm + wm + i * 16 + lr4;
            #pragma unroll
            for (int j = 0; j < 4; j++) {
                const int col = bn + wn + j * 8 + lk2;
                *(float2*)(C + (size_t)row * Nc + col) =
                    make_float2(d[i][j][0], d[i][j][1]);
                *(float2*)(C + (size_t)(row + 8) * Nc + col) =
                    make_float2(d[i][j][2], d[i][j][3]);
            }
        }
    }
}

// ---------------------------------------------------------------------------
// Flash attention, pure fp16, causal. 128-row KV stages (2 x 64-col subtiles),
// 2-stage cp.async prefetch, ex2.approx.f16x2 softmax.
// ---------------------------------------------------------------------------
#define FPAD 72
#define FTILE2 (128 * FPAD)                // halfs per 128-row K or V tile
#define FBUF_BYTES (2 * FTILE2 * 2)        // K,V = 36864 per stage
#define FLASH_SMEM (2 * FBUF_BYTES)        // 73728

__global__ __launch_bounds__(256) void flash_mma(
    const __half* __restrict__ qkvh,
    __half* __restrict__ ah)
{
    extern __shared__ __align__(16) char fsm[];

    const int tid  = threadIdx.x;
    const int lane = tid & 31;
    const int w    = tid >> 5;
    const int qi   = (int)gridDim.x - 1 - (int)blockIdx.x;
    const int by   = blockIdx.y;
    const int n    = by >> 4;
    const int h    = by & 15;
    const int q0   = qi * 128;
    const int lr4  = lane >> 2;
    const int lk2  = (lane & 3) * 2;

    const __half* qhp = qkvh + (size_t)n * F3 + h * D_HEAD;
    const __half* khp = qhp + E_DIM;
    const __half* vhp = qhp + 2 * E_DIM;

    // ---- Phase 1: stage Q in buffer 0 (128*FPAD*2 = 18432 <= 36864), frags --
    {
        __half* Qsh = (__half*)fsm;
        #pragma unroll
        for (int i = 0; i < 4; i++) {
            int ch = tid + i * 256;
            int r  = ch >> 3;
            int c  = (ch & 7) * 8;
            *(uint4*)&Qsh[r * FPAD + c] =
                *(const uint4*)(qhp + (size_t)(q0 + r) * QKV_ROW + c);
        }
    }
    __syncthreads();

    uint32_t qh[4][4];
    {
        const uint32_t qa = (uint32_t)(((w * 16 + (lane & 15)) * FPAD +
                                        (lane >> 4) * 8) * 2);
        const uint32_t sQh = smem_u32(fsm);
        #pragma unroll
        for (int st = 0; st < 4; st++)
            ldmx4(sQh + qa + st * 32, qh[st]);
    }
    __syncthreads();

    const __half* fsrc[2] = {khp, vhp};
    // 128-row stage: 2 arrays x 128 rows x 8 chunks = 2048 chunks = 8/thread
    auto load_tile = [&](int buf, int stg) {
        char* base = fsm + buf * FBUF_BYTES;
        #pragma unroll
        for (int i = 0; i < 8; i++) {
            int ch = tid + i * 256;
            int t  = ch >> 10;              // 0 = K, 1 = V
            int rr = (ch >> 3) & 127;
            int cc = (ch & 7) * 8;
            __half* dst = (__half*)base + t * FTILE2 + rr * FPAD + cc;
            cp_async16(smem_u32(dst),
                       fsrc[t] + (size_t)(stg * 128 + rr) * QKV_ROW + cc);
        }
        CP_COMMIT();
    };

    float rm0 = -1e30f, rm1 = -1e30f, rl0 = 0.0f, rl1 = 0.0f;
    float o[8][4];
    #pragma unroll
    for (int j = 0; j < 8; j++)
        #pragma unroll
        for (int r = 0; r < 4; r++) o[j][r] = 0.0f;

    const int nst = qi + 1;                 // 128-row stages
    load_tile(0, 0);

    for (int stg = 0; stg < nst; stg++) {
        const int b = stg & 1;
        CP_WAIT(0);
        __syncthreads();
        if (stg + 1 < nst) load_tile(b ^ 1, stg + 1);

        const __half* Kb = (const __half*)(fsm + b * FBUF_BYTES);
        const __half* Vb = Kb + FTILE2;

        #pragma unroll
        for (int sub = 0; sub < 2; sub++) {
            const int kt = stg * 2 + sub;   // 64-col logical tile index
            const __half* Kh = Kb + sub * 64 * FPAD;
            const __half* Vh = Vb + sub * 64 * FPAD;

            // ---- S = Q K^T ----
            float s[8][4];
            #pragma unroll
            for (int j = 0; j < 8; j++)
                #pragma unroll
                for (int r = 0; r < 4; r++) s[j][r] = 0.0f;

            #pragma unroll
            for (int st = 0; st < 4; st++) {
                const int kb = st * 16 + lk2;
                #pragma unroll
                for (int jp = 0; jp < 4; jp++) {
                    const int n0 = (2 * jp)     * 8 + lr4;
                    const int n1 = (2 * jp + 1) * 8 + lr4;
                    uint32_t bh0[2], bh1[2];
                    bh0[0] = *(const uint32_t*)(Kh + n0 * FPAD + kb);
                    bh0[1] = *(const uint32_t*)(Kh + n0 * FPAD + kb + 8);
                    bh1[0] = *(const uint32_t*)(Kh + n1 * FPAD + kb);
                    bh1[1] = *(const uint32_t*)(Kh + n1 * FPAD + kb + 8);
                    mma16816h(s[2*jp],   qh[st], bh0);
                    mma16816h(s[2*jp+1], qh[st], bh1);
                }
            }

            // ---- causal mask ----
            if (kt >= 2 * qi) {
                const int r0g = q0 + w * 16 + lr4;
                const int r1g = r0g + 8;
                #pragma unroll
                for (int j = 0; j < 8; j++) {
                    const int cg = kt * 64 + j * 8 + lk2;
                    if (cg     > r0g) s[j][0] = -1e30f;
                    if (cg + 1 > r0g) s[j][1] = -1e30f;
                    if (cg     > r1g) s[j][2] = -1e30f;
                    if (cg + 1 > r1g) s[j][3] = -1e30f;
                }
            }

            // ---- online softmax (row max in fp32) ----
            float mx0 = -1e30f, mx1 = -1e30f;
            #pragma unroll
            for (int j = 0; j < 8; j++) {
                mx0 = fmaxf(mx0, fmaxf(s[j][0], s[j][1]));
                mx1 = fmaxf(mx1, fmaxf(s[j][2], s[j][3]));
            }
            mx0 = fmaxf(mx0, __shfl_xor_sync(0xffffffffu, mx0, 1));
            mx0 = fmaxf(mx0, __shfl_xor_sync(0xffffffffu, mx0, 2));
            mx1 = fmaxf(mx1, __shfl_xor_sync(0xffffffffu, mx1, 1));
            mx1 = fmaxf(mx1, __shfl_xor_sync(0xffffffffu, mx1, 2));

            const float mn0 = fmaxf(rm0, mx0);
            const float mn1 = fmaxf(rm1, mx1);
            const float a0 = __expf(rm0 - mn0);
            const float a1 = __expf(rm1 - mn1);
            rm0 = mn0; rm1 = mn1;

            // ---- P = exp(S - m) via ex2.approx.f16x2 ----
            uint32_t p[8][2];
            float sum0 = 0.0f, sum1 = 0.0f;
            #pragma unroll
            for (int j = 0; j < 8; j++) {
                __half2 e0 = __floats2half2_rn((s[j][0] - mn0) * LOG2E_F,
                                               (s[j][1] - mn0) * LOG2E_F);
                __half2 e1 = __floats2half2_rn((s[j][2] - mn1) * LOG2E_F,
                                               (s[j][3] - mn1) * LOG2E_F);
                p[j][0] = h2exp2u(*(uint32_t*)&e0);
                p[j][1] = h2exp2u(*(uint32_t*)&e1);
                float2 f0 = __half22float2(*(__half2*)&p[j][0]);
                float2 f1 = __half22float2(*(__half2*)&p[j][1]);
                sum0 += f0.x + f0.y;
                sum1 += f1.x + f1.y;
            }
            sum0 += __shfl_xor_sync(0xffffffffu, sum0, 1);
            sum0 += __shfl_xor_sync(0xffffffffu, sum0, 2);
            sum1 += __shfl_xor_sync(0xffffffffu, sum1, 1);
            sum1 += __shfl_xor_sync(0xffffffffu, sum1, 2);
            rl0 = rl0 * a0 + sum0;
            rl1 = rl1 * a1 + sum1;

            #pragma unroll
            for (int j = 0; j < 8; j++) {
                o[j][0] *= a0; o[j][1] *= a0;
                o[j][2] *= a1; o[j][3] *= a1;
            }

            // ---- O += P V ----
            #pragma unroll
            for (int st = 0; st < 4; st++) {
                uint32_t pah[4];
                pah[0] = p[2*st][0];
                pah[1] = p[2*st][1];
                pah[2] = p[2*st+1][0];
                pah[3] = p[2*st+1][1];
                const int vrow = st * 16 + (lane & 15);
                #pragma unroll
                for (int jp = 0; jp < 4; jp++) {
                    const int j0 = 2 * jp, j1 = 2 * jp + 1;
                    uint32_t bh0[2], bh1[2];
                    ldmx2t(smem_u32(Vh + vrow * FPAD + j0 * 8), bh0);
                    ldmx2t(smem_u32(Vh + vrow * FPAD + j1 * 8), bh1);
                    mma16816h(o[j0], pah, bh0);
                    mma16816h(o[j1], pah, bh1);
                }
            }
        }
    }

    // ---- epilogue: normalize, write fp16 ----
    const float inv0 = 1.0f / rl0;
    const float inv1 = 1.0f / rl1;
    const int r0g = q0 + w * 16 + lr4;
    const size_t row0 = (size_t)(r0g * N_BATCH + n) * E_DIM;
    const size_t row1 = (size_t)((r0g + 8) * N_BATCH + n) * E_DIM;
    #pragma unroll
    for (int j = 0; j < 8; j++) {
        const int col = h * D_HEAD + j * 8 + lk2;
        *(uint32_t*)(ah + row0 + col) = pack2h(o[j][0] * inv0, o[j][1] * inv0);
        *(uint32_t*)(ah + row1 + col) = pack2h(o[j][2] * inv1, o[j][3] * inv1);
    }
}

// ---------------------------------------------------------------------------
extern "C" void kernel_launch(void* const* d_in, const int* in_sizes, int n_in,
                              void* d_out, int out_size)
{
    const float* x     = (const float*)d_in[0];
    const float* w_qkv = (const float*)d_in[1];
    const float* w_out = (const float*)d_in[2];
    float* out = (float*)d_out;

    __half *qkvh, *xh, *wqh, *woh, *ah;
    cudaGetSymbolAddress((void**)&qkvh, g_qkvh);
    cudaGetSymbolAddress((void**)&xh,   g_xh);
    cudaGetSymbolAddress((void**)&wqh,  g_wqh);
    cudaGetSymbolAddress((void**)&woh,  g_woh);
    cudaGetSymbolAddress((void**)&ah,   g_ah);

    cudaFuncSetAttribute(gemm_mma,
                         cudaFuncAttributeMaxDynamicSharedMemorySize, GEMM_SMEM);
    cudaFuncSetAttribute(flash_mma,
                         cudaFuncAttributeMaxDynamicSharedMemorySize, FLASH_SMEM);

    // 0) fused conversions
    {
        int total = NX4 + NWQ4 + NWO4;
        convert_all<<<(total + 255) / 256, 256>>>(x, w_qkv, w_out, xh, wqh, woh);
    }

    // 1) QKV projection -> fp16 (Q region scaled by 1/8)
    gemm_mma<<<dim3(F3 / 128, ROWS_TOT / 256), 512, GEMM_SMEM>>>(
        xh, wqh, nullptr, qkvh, 1, E_DIM, ROWS_TOT, F3, E_DIM);

    // 2) Causal flash attention -> fp16
    flash_mma<<<dim3(L_SEQ / 128, N_BATCH * H_HEADS), 256, FLASH_SMEM>>>(
        qkvh, ah);

    // 3) Output projection -> fp32 out
    gemm_mma<<<dim3(E_DIM / 128, ROWS_TOT / 256), 512, GEMM_SMEM>>>(
        ah, woh, out, nullptr, 0, 0, ROWS_TOT, E_DIM, E_DIM);
}